// round 2
// baseline (speedup 1.0000x reference)
#include <cuda_runtime.h>
#include <cstddef>

#define Nn 20000
#define Ee 256
#define Hh 512
#define Ll 5

// ---------------- scratch (device globals; no allocations allowed) ----------
__device__ float g_h[Nn * Ee];     // current node features
__device__ float g_agg[Nn * Ee];   // aggregation buffer
__device__ float g_pre[Nn * Ee];   // (1+eps)*xs + agg
__device__ float g_t1[Nn * Hh];    // hidden after W1
__device__ float g_hB[Nn * Ee];    // after W2, pre-outer-BN
__device__ float g_sumsH[2 * Hh];  // col sum / sumsq for H-wide BN
__device__ float g_sumsE[2 * Ee];
__device__ float g_scaleH[Hh];
__device__ float g_shiftH[Hh];
__device__ float g_scaleE[Ee];
__device__ float g_shiftE[Ee];
__device__ float g_mask[Nn];       // mask normalized to float 0/1
__device__ int   g_mask_dtype;     // 0=int32, 1=float32, 2=uint8

// ---------------- mask dtype detection -------------------------------------
// Scans the first 5000 32-bit words (20KB, safe for any dtype of a 20000-elem
// array). int32 0/1 data -> all words in {0,1}. float32 0/1.0 -> words in
// {0, 0x3F800000}. packed uint8 0/1 -> mixed-byte words (e.g. 0x00010001).
__global__ void detect_mask_k(const void* mask) {
    __shared__ int not_i32, not_f32;
    if (threadIdx.x == 0) { not_i32 = 0; not_f32 = 0; }
    __syncthreads();
    const unsigned* w = (const unsigned*)mask;
    int bad_i = 0, bad_f = 0;
    for (int i = threadIdx.x; i < Nn / 4; i += blockDim.x) {
        unsigned v = w[i];
        if (v > 1u) bad_i = 1;
        if (v != 0u && v != 0x3F800000u) bad_f = 1;
    }
    if (bad_i) atomicOr(&not_i32, 1);
    if (bad_f) atomicOr(&not_f32, 1);
    __syncthreads();
    if (threadIdx.x == 0) {
        if (!not_i32) g_mask_dtype = 0;
        else if (!not_f32) g_mask_dtype = 1;
        else g_mask_dtype = 2;
    }
}

__global__ void convert_mask_k(const void* mask) {
    int n = blockIdx.x * blockDim.x + threadIdx.x;
    if (n >= Nn) return;
    int dt = g_mask_dtype;
    float m;
    if (dt == 0)      m = (((const int*)mask)[n] != 0) ? 1.f : 0.f;
    else if (dt == 1) m = (((const float*)mask)[n] != 0.f) ? 1.f : 0.f;
    else              m = (((const unsigned char*)mask)[n] != 0) ? 1.f : 0.f;
    g_mask[n] = m;
}

// ---------------- kernels ---------------------------------------------------

// zero agg + stat accumulators
__global__ void prep_zero_k() {
    int i = blockIdx.x * blockDim.x + threadIdx.x;
    if (i < Nn * Ee / 4) ((float4*)g_agg)[i] = make_float4(0.f, 0.f, 0.f, 0.f);
    if (i < 2 * Hh) g_sumsH[i] = 0.f;
    if (i < 2 * Ee) g_sumsE[i] = 0.f;
}

// AtomEncoder: h[n,:] = sum_f atom_emb[f, x[n,f], :]
__global__ void atom_encode_k(const int* __restrict__ x,
                              const float* __restrict__ emb,
                              float* __restrict__ h) {
    int n = blockIdx.x;
    int t = threadIdx.x;  // 64 threads, float4 each -> 256 cols
    float4 acc = make_float4(0.f, 0.f, 0.f, 0.f);
#pragma unroll
    for (int f = 0; f < 9; f++) {
        int idx = __ldg(&x[n * 9 + f]);
        const float4* row = (const float4*)&emb[((size_t)(f * 128 + idx)) * Ee];
        float4 v = row[t];
        acc.x += v.x; acc.y += v.y; acc.z += v.z; acc.w += v.w;
    }
    ((float4*)h)[(size_t)n * (Ee / 4) + t] = acc;
}

// graph-edge scatter: msg = relu(h[src] + bond_emb(attr)); atomicAdd into agg[dst]
__global__ void scatter_bond_k(const float* __restrict__ h,
                               const int* __restrict__ src,
                               const int* __restrict__ dst,
                               const int* __restrict__ attr,
                               const float* __restrict__ bemb,
                               float* __restrict__ agg, int M) {
    int w = (blockIdx.x * blockDim.x + threadIdx.x) >> 5;
    int lane = threadIdx.x & 31;
    if (w >= M) return;
    int s  = __ldg(&src[w]);
    int d  = __ldg(&dst[w]);
    int a0 = __ldg(&attr[w * 3 + 0]);
    int a1 = __ldg(&attr[w * 3 + 1]);
    int a2 = __ldg(&attr[w * 3 + 2]);
    const float* hs = h + (size_t)s * Ee;
    const float* e0 = bemb + (size_t)(0 * 8 + a0) * Ee;
    const float* e1 = bemb + (size_t)(1 * 8 + a1) * Ee;
    const float* e2 = bemb + (size_t)(2 * 8 + a2) * Ee;
    float* ag = agg + (size_t)d * Ee;
#pragma unroll
    for (int j = 0; j < 8; j++) {
        int e = lane + j * 32;
        float v = __ldg(&hs[e]) + __ldg(&e0[e]) + __ldg(&e1[e]) + __ldg(&e2[e]);
        atomicAdd(&ag[e], fmaxf(v, 0.f));
    }
}

// expander scatter: msg = relu(h[src]); atomicAdd into agg[dst]
__global__ void scatter_plain_k(const float* __restrict__ h,
                                const int* __restrict__ src,
                                const int* __restrict__ dst,
                                float* __restrict__ agg, int M) {
    int w = (blockIdx.x * blockDim.x + threadIdx.x) >> 5;
    int lane = threadIdx.x & 31;
    if (w >= M) return;
    int s = __ldg(&src[w]);
    int d = __ldg(&dst[w]);
    const float* hs = h + (size_t)s * Ee;
    float* ag = agg + (size_t)d * Ee;
#pragma unroll
    for (int j = 0; j < 8; j++) {
        int e = lane + j * 32;
        atomicAdd(&ag[e], fmaxf(__ldg(&hs[e]), 0.f));
    }
}

// pre = (1+eps) * (h * mask?) + agg
__global__ void combine_k(const float* __restrict__ h,
                          const float* __restrict__ agg,
                          const float* __restrict__ mask,
                          const float* __restrict__ eps,
                          float* __restrict__ pre) {
    int i = blockIdx.x * blockDim.x + threadIdx.x;
    if (i >= Nn * Ee / 4) return;
    float e1 = 1.f + __ldg(eps);
    float4 xv = ((const float4*)h)[i];
    if (mask) {
        float m = mask[i >> 6];  // node = (i*4)/256
        xv.x *= m; xv.y *= m; xv.z *= m; xv.w *= m;
    }
    float4 av = ((const float4*)agg)[i];
    float4 o;
    o.x = fmaf(e1, xv.x, av.x);
    o.y = fmaf(e1, xv.y, av.y);
    o.z = fmaf(e1, xv.z, av.z);
    o.w = fmaf(e1, xv.w, av.w);
    ((float4*)pre)[i] = o;
}

// SGEMM C[Mr,Nc] = op(A)[Mr,K] @ B[K,Nc] + bias
// BNA: apply per-K-column affine + relu to A on load (fused BN1+ReLU for GEMM2)
template <bool BNA>
__global__ __launch_bounds__(256) void sgemm_k(
    const float* __restrict__ A, const float* __restrict__ B,
    const float* __restrict__ bias,
    const float* __restrict__ ascale, const float* __restrict__ ashift,
    float* __restrict__ C, int Mr, int K, int Nc) {
    __shared__ float As[8][128];
    __shared__ float Bs[8][128];

    const int tid = threadIdx.x;
    const int tx = tid & 15, ty = tid >> 4;
    const int arow = tid >> 1;           // 0..127
    const int acol = (tid & 1) * 4;      // 0 or 4
    const int brow = tid >> 5;           // 0..7
    const int bcol = (tid & 31) * 4;     // 0..124
    const int gArow = blockIdx.y * 128 + arow;
    const int gBcol0 = blockIdx.x * 128;

    float acc[8][8];
#pragma unroll
    for (int i = 0; i < 8; i++)
#pragma unroll
        for (int j = 0; j < 8; j++) acc[i][j] = 0.f;

    for (int k0 = 0; k0 < K; k0 += 8) {
        float4 av = make_float4(0.f, 0.f, 0.f, 0.f);
        if (gArow < Mr)
            av = *(const float4*)&A[(size_t)gArow * K + k0 + acol];
        if (BNA) {
            int kk = k0 + acol;
            av.x = fmaxf(fmaf(av.x, ascale[kk + 0], ashift[kk + 0]), 0.f);
            av.y = fmaxf(fmaf(av.y, ascale[kk + 1], ashift[kk + 1]), 0.f);
            av.z = fmaxf(fmaf(av.z, ascale[kk + 2], ashift[kk + 2]), 0.f);
            av.w = fmaxf(fmaf(av.w, ascale[kk + 3], ashift[kk + 3]), 0.f);
        }
        As[acol + 0][arow] = av.x;
        As[acol + 1][arow] = av.y;
        As[acol + 2][arow] = av.z;
        As[acol + 3][arow] = av.w;

        float4 bv = *(const float4*)&B[(size_t)(k0 + brow) * Nc + gBcol0 + bcol];
        *(float4*)&Bs[brow][bcol] = bv;
        __syncthreads();

#pragma unroll
        for (int kk = 0; kk < 8; kk++) {
            float a[8], b[8];
            *(float4*)&a[0] = *(const float4*)&As[kk][ty * 8];
            *(float4*)&a[4] = *(const float4*)&As[kk][ty * 8 + 4];
            *(float4*)&b[0] = *(const float4*)&Bs[kk][tx * 8];
            *(float4*)&b[4] = *(const float4*)&Bs[kk][tx * 8 + 4];
#pragma unroll
            for (int i = 0; i < 8; i++)
#pragma unroll
                for (int j = 0; j < 8; j++) acc[i][j] = fmaf(a[i], b[j], acc[i][j]);
        }
        __syncthreads();
    }

    float bb[8];
#pragma unroll
    for (int j = 0; j < 8; j++)
        bb[j] = bias ? __ldg(&bias[gBcol0 + tx * 8 + j]) : 0.f;

#pragma unroll
    for (int i = 0; i < 8; i++) {
        int r = blockIdx.y * 128 + ty * 8 + i;
        if (r < Mr) {
            float* cp = &C[(size_t)r * Nc + gBcol0 + tx * 8];
            float4 v0 = make_float4(acc[i][0] + bb[0], acc[i][1] + bb[1],
                                    acc[i][2] + bb[2], acc[i][3] + bb[3]);
            float4 v1 = make_float4(acc[i][4] + bb[4], acc[i][5] + bb[5],
                                    acc[i][6] + bb[6], acc[i][7] + bb[7]);
            *(float4*)&cp[0] = v0;
            *(float4*)&cp[4] = v1;
        }
    }
}

// per-column sum & sumsq over Nn rows
__global__ void colstats_k(const float* __restrict__ X, int C, float* __restrict__ sums) {
    int col = blockIdx.x * 32 + threadIdx.x;
    float s = 0.f, s2 = 0.f;
    for (int r = blockIdx.y * 8 + threadIdx.y; r < Nn; r += gridDim.y * 8) {
        float v = X[(size_t)r * C + col];
        s += v;
        s2 += v * v;
    }
    __shared__ float sh[2][8][32];
    sh[0][threadIdx.y][threadIdx.x] = s;
    sh[1][threadIdx.y][threadIdx.x] = s2;
    __syncthreads();
    if (threadIdx.y == 0) {
#pragma unroll
        for (int k = 1; k < 8; k++) {
            s += sh[0][k][threadIdx.x];
            s2 += sh[1][k][threadIdx.x];
        }
        atomicAdd(&sums[col], s);
        atomicAdd(&sums[C + col], s2);
    }
}

// BN stats -> per-column scale/shift  (y = x*scale + shift)
__global__ void bn_finalize_k(const float* __restrict__ sums,
                              const float* __restrict__ g,
                              const float* __restrict__ be,
                              float* __restrict__ scale, float* __restrict__ shift, int C) {
    int c = blockIdx.x * blockDim.x + threadIdx.x;
    if (c >= C) return;
    float mean = sums[c] * (1.f / Nn);
    float var = sums[C + c] * (1.f / Nn) - mean * mean;
    float sc = g[c] * rsqrtf(var + 1e-5f);
    scale[c] = sc;
    shift[c] = be[c] - mean * sc;
}

// h = (relu?)(X*scale[c] + shift[c])
__global__ void bn_apply_k(const float* __restrict__ X,
                           const float* __restrict__ scale,
                           const float* __restrict__ shift,
                           float* __restrict__ Y, int do_relu) {
    int i = blockIdx.x * blockDim.x + threadIdx.x;
    if (i >= Nn * Ee / 4) return;
    int c = (i & 63) * 4;
    float4 v = ((const float4*)X)[i];
    v.x = fmaf(v.x, scale[c + 0], shift[c + 0]);
    v.y = fmaf(v.y, scale[c + 1], shift[c + 1]);
    v.z = fmaf(v.z, scale[c + 2], shift[c + 2]);
    v.w = fmaf(v.w, scale[c + 3], shift[c + 3]);
    if (do_relu) {
        v.x = fmaxf(v.x, 0.f); v.y = fmaxf(v.y, 0.f);
        v.z = fmaxf(v.z, 0.f); v.w = fmaxf(v.w, 0.f);
    }
    ((float4*)Y)[i] = v;
}

// ---------------- host orchestration ---------------------------------------

struct Scratch {
    float *h, *agg, *pre, *t1, *hB;
    float *sumsH, *sumsE, *scaleH, *shiftH, *scaleE, *shiftE, *mask;
};

static void run_conv(const Scratch& S,
                     const int* src, const int* dst, int M,
                     const int* attr, const float* bemb,         // null => expander conv
                     const float* eps,
                     const float* W1, const float* b1,
                     const float* g1, const float* be1,
                     const float* W2, const float* b2,
                     const float* bn_g, const float* bn_b,
                     const float* mask,                          // null => no masking
                     int relu_out) {
    prep_zero_k<<<(Nn * Ee / 4 + 255) / 256, 256>>>();

    int warps_blocks = (M * 32 + 255) / 256;
    if (attr)
        scatter_bond_k<<<warps_blocks, 256>>>(S.h, src, dst, attr, bemb, S.agg, M);
    else
        scatter_plain_k<<<warps_blocks, 256>>>(S.h, src, dst, S.agg, M);

    combine_k<<<(Nn * Ee / 4 + 255) / 256, 256>>>(S.h, S.agg, mask, eps, S.pre);

    dim3 g1d(Hh / 128, (Nn + 127) / 128);
    sgemm_k<false><<<g1d, 256>>>(S.pre, W1, b1, nullptr, nullptr, S.t1, Nn, Ee, Hh);

    colstats_k<<<dim3(Hh / 32, 40), dim3(32, 8)>>>(S.t1, Hh, S.sumsH);
    bn_finalize_k<<<(Hh + 255) / 256, 256>>>(S.sumsH, g1, be1, S.scaleH, S.shiftH, Hh);

    dim3 g2d(Ee / 128, (Nn + 127) / 128);
    sgemm_k<true><<<g2d, 256>>>(S.t1, W2, b2, S.scaleH, S.shiftH, S.hB, Nn, Hh, Ee);

    colstats_k<<<dim3(Ee / 32, 40), dim3(32, 8)>>>(S.hB, Ee, S.sumsE);
    bn_finalize_k<<<(Ee + 255) / 256, 256>>>(S.sumsE, bn_g, bn_b, S.scaleE, S.shiftE, Ee);

    bn_apply_k<<<(Nn * Ee / 4 + 255) / 256, 256>>>(S.hB, S.scaleE, S.shiftE, S.h, relu_out);
}

extern "C" void kernel_launch(void* const* d_in, const int* in_sizes, int n_in,
                              void* d_out, int out_size) {
    const int* x       = (const int*)d_in[0];
    const int* ei      = (const int*)d_in[1];
    const int* ea      = (const int*)d_in[2];
    const int* xei     = (const int*)d_in[3];
    const void* mask_raw = d_in[4];
    const float* atom_emb = (const float*)d_in[5];
    const float* bond_emb = (const float*)d_in[6];
    const float* eps_m = (const float*)d_in[7];
    const float* W1_m  = (const float*)d_in[8];
    const float* b1_m  = (const float*)d_in[9];
    const float* g1_m  = (const float*)d_in[10];
    const float* be1_m = (const float*)d_in[11];
    const float* W2_m  = (const float*)d_in[12];
    const float* b2_m  = (const float*)d_in[13];
    const float* bn_g_m = (const float*)d_in[14];
    const float* bn_b_m = (const float*)d_in[15];
    const float* eps_e = (const float*)d_in[16];
    const float* W1_e  = (const float*)d_in[17];
    const float* g1_e  = (const float*)d_in[18];
    const float* be1_e = (const float*)d_in[19];
    const float* W2_e  = (const float*)d_in[20];
    const float* bn_g_e = (const float*)d_in[21];
    const float* bn_b_e = (const float*)d_in[22];

    const int M  = in_sizes[1] / 2;
    const int MX = in_sizes[3] / 2;

    Scratch S;
    cudaGetSymbolAddress((void**)&S.h, g_h);
    cudaGetSymbolAddress((void**)&S.agg, g_agg);
    cudaGetSymbolAddress((void**)&S.pre, g_pre);
    cudaGetSymbolAddress((void**)&S.t1, g_t1);
    cudaGetSymbolAddress((void**)&S.hB, g_hB);
    cudaGetSymbolAddress((void**)&S.sumsH, g_sumsH);
    cudaGetSymbolAddress((void**)&S.sumsE, g_sumsE);
    cudaGetSymbolAddress((void**)&S.scaleH, g_scaleH);
    cudaGetSymbolAddress((void**)&S.shiftH, g_shiftH);
    cudaGetSymbolAddress((void**)&S.scaleE, g_scaleE);
    cudaGetSymbolAddress((void**)&S.shiftE, g_shiftE);
    cudaGetSymbolAddress((void**)&S.mask, g_mask);

    const int* src  = ei;
    const int* dstp = ei + M;
    const int* esrc = xei;
    const int* edst = xei + MX;

    // normalize mask dtype -> float 0/1
    detect_mask_k<<<1, 256>>>(mask_raw);
    convert_mask_k<<<(Nn + 255) / 256, 256>>>(mask_raw);

    atom_encode_k<<<Nn, 64>>>(x, atom_emb, S.h);

    for (int l = 0; l < Ll; l++) {
        // graph-edge conv (bond embeddings, biases, no mask, relu out)
        run_conv(S, src, dstp, M, ea, bond_emb,
                 eps_m + l,
                 W1_m + (size_t)l * Ee * Hh, b1_m + (size_t)l * Hh,
                 g1_m + (size_t)l * Hh, be1_m + (size_t)l * Hh,
                 W2_m + (size_t)l * Hh * Ee, b2_m + (size_t)l * Ee,
                 bn_g_m + (size_t)l * Ee, bn_b_m + (size_t)l * Ee,
                 nullptr, 1);

        int s0 = l * 2, s1 = l * 2 + 1;
        // expander left conv (esrc -> edst), mask, no biases, relu out
        run_conv(S, esrc, edst, MX, nullptr, nullptr,
                 eps_e + s0,
                 W1_e + (size_t)s0 * Ee * Hh, nullptr,
                 g1_e + (size_t)s0 * Hh, be1_e + (size_t)s0 * Hh,
                 W2_e + (size_t)s0 * Hh * Ee, nullptr,
                 bn_g_e + (size_t)s0 * Ee, bn_b_e + (size_t)s0 * Ee,
                 S.mask, 1);

        // expander right conv (edst -> esrc), mask, relu only if not last layer
        run_conv(S, edst, esrc, MX, nullptr, nullptr,
                 eps_e + s1,
                 W1_e + (size_t)s1 * Ee * Hh, nullptr,
                 g1_e + (size_t)s1 * Hh, be1_e + (size_t)s1 * Hh,
                 W2_e + (size_t)s1 * Hh * Ee, nullptr,
                 bn_g_e + (size_t)s1 * Ee, bn_b_e + (size_t)s1 * Ee,
                 S.mask, (l < Ll - 1) ? 1 : 0);
    }

    cudaMemcpyAsync(d_out, S.h, (size_t)Nn * Ee * sizeof(float),
                    cudaMemcpyDeviceToDevice, 0);
}

// round 4
// speedup vs baseline: 1.7045x; 1.7045x over previous
#include <cuda_runtime.h>
#include <cuda_bf16.h>
#include <cstddef>
#include <cstdint>

#define Nn 20000
#define Ee 256
#define Hh 512
#define Ll 5
#define NCONV 15

// ---------------- scratch (device globals; no allocations allowed) ----------
__device__ float g_h[Nn * Ee];
__device__ float g_agg[Nn * Ee];
__device__ float g_t1[Nn * Hh];
__device__ float g_hB[Nn * Ee];
__device__ float g_sumsH[2 * Hh];
__device__ float g_sumsE[2 * Ee];
__device__ float g_scaleH[Hh];
__device__ float g_shiftH[Hh];
__device__ float g_scaleE[Ee];
__device__ float g_shiftE[Ee];
__device__ float g_mask[Nn];
__device__ int   g_mask_dtype;

// bf16 split operands
__device__ __nv_bfloat16 g_A1hi[Nn * Ee];
__device__ __nv_bfloat16 g_A1lo[Nn * Ee];
__device__ __nv_bfloat16 g_A2hi[Nn * Hh];
__device__ __nv_bfloat16 g_A2lo[Nn * Hh];
// pre-transposed weights: W1T[c]: [Hh rows, Ee cols]; W2T[c]: [Ee rows, Hh cols]
__device__ __nv_bfloat16 g_W1Thi[NCONV * Hh * Ee];
__device__ __nv_bfloat16 g_W1Tlo[NCONV * Hh * Ee];
__device__ __nv_bfloat16 g_W2Thi[NCONV * Ee * Hh];
__device__ __nv_bfloat16 g_W2Tlo[NCONV * Ee * Hh];

// ---------------- helpers ----------------------------------------------------
__device__ __forceinline__ uint32_t smem_u32(const void* p) {
    uint32_t a;
    asm("{ .reg .u64 t; cvta.to.shared.u64 t, %1; cvt.u32.u64 %0, t; }" : "=r"(a) : "l"(p));
    return a;
}
#define SW128(off) ((off) ^ (((off) >> 3) & 0x70))

#define LDSM_X4(r0, r1, r2, r3, addr) \
    asm volatile("ldmatrix.sync.aligned.m8n8.x4.shared.b16 {%0,%1,%2,%3}, [%4];" \
                 : "=r"(r0), "=r"(r1), "=r"(r2), "=r"(r3) : "r"(addr))

#define MMA16816(d, a0, a1, a2, a3, b0, b1) \
    asm volatile("mma.sync.aligned.m16n8k16.row.col.f32.bf16.bf16.f32 " \
                 "{%0,%1,%2,%3}, {%4,%5,%6,%7}, {%8,%9}, {%0,%1,%2,%3};" \
                 : "+f"((d)[0]), "+f"((d)[1]), "+f"((d)[2]), "+f"((d)[3]) \
                 : "r"(a0), "r"(a1), "r"(a2), "r"(a3), "r"(b0), "r"(b1))

// ---------------- mask dtype handling ---------------------------------------
__global__ void detect_mask_k(const void* mask) {
    __shared__ int not_i32, not_f32;
    if (threadIdx.x == 0) { not_i32 = 0; not_f32 = 0; }
    __syncthreads();
    const unsigned* w = (const unsigned*)mask;
    int bad_i = 0, bad_f = 0;
    for (int i = threadIdx.x; i < Nn / 4; i += blockDim.x) {
        unsigned v = w[i];
        if (v > 1u) bad_i = 1;
        if (v != 0u && v != 0x3F800000u) bad_f = 1;
    }
    if (bad_i) atomicOr(&not_i32, 1);
    if (bad_f) atomicOr(&not_f32, 1);
    __syncthreads();
    if (threadIdx.x == 0) {
        if (!not_i32) g_mask_dtype = 0;
        else if (!not_f32) g_mask_dtype = 1;
        else g_mask_dtype = 2;
    }
}
__global__ void convert_mask_k(const void* mask) {
    int n = blockIdx.x * blockDim.x + threadIdx.x;
    if (n >= Nn) return;
    int dt = g_mask_dtype;
    float m;
    if (dt == 0)      m = (((const int*)mask)[n] != 0) ? 1.f : 0.f;
    else if (dt == 1) m = (((const float*)mask)[n] != 0.f) ? 1.f : 0.f;
    else              m = (((const unsigned char*)mask)[n] != 0) ? 1.f : 0.f;
    g_mask[n] = m;
}

// ---------------- weight transpose + bf16 split -----------------------------
// W [K,N] fp32 -> WT hi/lo [N,K] bf16
__global__ void wsplit_k(const float* __restrict__ W,
                         __nv_bfloat16* __restrict__ Thi,
                         __nv_bfloat16* __restrict__ Tlo, int K, int N) {
    __shared__ float t[32][33];
    int kb = blockIdx.x * 32, nb = blockIdx.y * 32;
    int tx = threadIdx.x, ty = threadIdx.y;
    for (int i = ty; i < 32; i += 8)
        t[i][tx] = W[(size_t)(kb + i) * N + nb + tx];
    __syncthreads();
    for (int i = ty; i < 32; i += 8) {
        float v = t[tx][i];  // = W[kb+tx][nb+i]
        __nv_bfloat16 hi = __float2bfloat16(v);
        float lo = v - __bfloat162float(hi);
        Thi[(size_t)(nb + i) * K + kb + tx] = hi;
        Tlo[(size_t)(nb + i) * K + kb + tx] = __float2bfloat16(lo);
    }
}

// ---------------- misc kernels ----------------------------------------------
__global__ void prep_zero_k() {
    int i = blockIdx.x * blockDim.x + threadIdx.x;
    if (i < Nn * Ee / 4) ((float4*)g_agg)[i] = make_float4(0.f, 0.f, 0.f, 0.f);
    if (i < 2 * Hh) g_sumsH[i] = 0.f;
    if (i < 2 * Ee) g_sumsE[i] = 0.f;
}

__global__ void atom_encode_k(const int* __restrict__ x,
                              const float* __restrict__ emb,
                              float* __restrict__ h) {
    int n = blockIdx.x;
    int t = threadIdx.x;
    float4 acc = make_float4(0.f, 0.f, 0.f, 0.f);
#pragma unroll
    for (int f = 0; f < 9; f++) {
        int idx = __ldg(&x[n * 9 + f]);
        const float4* row = (const float4*)&emb[((size_t)(f * 128 + idx)) * Ee];
        float4 v = row[t];
        acc.x += v.x; acc.y += v.y; acc.z += v.z; acc.w += v.w;
    }
    ((float4*)h)[(size_t)n * (Ee / 4) + t] = acc;
}

__global__ void scatter_bond_k(const float* __restrict__ h,
                               const int* __restrict__ src,
                               const int* __restrict__ dst,
                               const int* __restrict__ attr,
                               const float* __restrict__ bemb,
                               float* __restrict__ agg, int M) {
    int w = (blockIdx.x * blockDim.x + threadIdx.x) >> 5;
    int lane = threadIdx.x & 31;
    if (w >= M) return;
    int s  = __ldg(&src[w]);
    int d  = __ldg(&dst[w]);
    int a0 = __ldg(&attr[w * 3 + 0]);
    int a1 = __ldg(&attr[w * 3 + 1]);
    int a2 = __ldg(&attr[w * 3 + 2]);
    const float* hs = h + (size_t)s * Ee;
    const float* e0 = bemb + (size_t)(0 * 8 + a0) * Ee;
    const float* e1 = bemb + (size_t)(1 * 8 + a1) * Ee;
    const float* e2 = bemb + (size_t)(2 * 8 + a2) * Ee;
    float* ag = agg + (size_t)d * Ee;
#pragma unroll
    for (int j = 0; j < 8; j++) {
        int e = lane + j * 32;
        float v = __ldg(&hs[e]) + __ldg(&e0[e]) + __ldg(&e1[e]) + __ldg(&e2[e]);
        atomicAdd(&ag[e], fmaxf(v, 0.f));
    }
}

__global__ void scatter_plain_k(const float* __restrict__ h,
                                const int* __restrict__ src,
                                const int* __restrict__ dst,
                                float* __restrict__ agg, int M) {
    int w = (blockIdx.x * blockDim.x + threadIdx.x) >> 5;
    int lane = threadIdx.x & 31;
    if (w >= M) return;
    int s = __ldg(&src[w]);
    int d = __ldg(&dst[w]);
    const float* hs = h + (size_t)s * Ee;
    float* ag = agg + (size_t)d * Ee;
#pragma unroll
    for (int j = 0; j < 8; j++) {
        int e = lane + j * 32;
        atomicAdd(&ag[e], fmaxf(__ldg(&hs[e]), 0.f));
    }
}

__device__ __forceinline__ uint32_t pack2bf(float a, float b, float* ra, float* rb) {
    __nv_bfloat16 ha = __float2bfloat16(a), hb = __float2bfloat16(b);
    *ra = a - __bfloat162float(ha);
    *rb = b - __bfloat162float(hb);
    return (uint32_t)__bfloat16_as_ushort(ha) | ((uint32_t)__bfloat16_as_ushort(hb) << 16);
}
__device__ __forceinline__ uint32_t pack2bf_only(float a, float b) {
    __nv_bfloat16 ha = __float2bfloat16(a), hb = __float2bfloat16(b);
    return (uint32_t)__bfloat16_as_ushort(ha) | ((uint32_t)__bfloat16_as_ushort(hb) << 16);
}

// pre = (1+eps)*(h*mask?) + agg  -> split to bf16 hi/lo (GEMM1 A operand)
__global__ void combine_split_k(const float* __restrict__ h,
                                const float* __restrict__ agg,
                                const float* __restrict__ mask,
                                const float* __restrict__ eps,
                                __nv_bfloat16* __restrict__ Ahi,
                                __nv_bfloat16* __restrict__ Alo) {
    int i = blockIdx.x * blockDim.x + threadIdx.x;
    if (i >= Nn * Ee / 4) return;
    float e1 = 1.f + __ldg(eps);
    float4 xv = ((const float4*)h)[i];
    if (mask) {
        float m = mask[i >> 6];
        xv.x *= m; xv.y *= m; xv.z *= m; xv.w *= m;
    }
    float4 av = ((const float4*)agg)[i];
    float4 o;
    o.x = fmaf(e1, xv.x, av.x);
    o.y = fmaf(e1, xv.y, av.y);
    o.z = fmaf(e1, xv.z, av.z);
    o.w = fmaf(e1, xv.w, av.w);
    float rx, ry, rz, rw;
    uint2 hi, lo;
    hi.x = pack2bf(o.x, o.y, &rx, &ry);
    hi.y = pack2bf(o.z, o.w, &rz, &rw);
    lo.x = pack2bf_only(rx, ry);
    lo.y = pack2bf_only(rz, rw);
    ((uint2*)Ahi)[i] = hi;
    ((uint2*)Alo)[i] = lo;
}

// t1 -> BN(scale,shift) -> relu -> split bf16 hi/lo (GEMM2 A operand)
__global__ void bnrelu_split_k(const float* __restrict__ X,
                               const float* __restrict__ scale,
                               const float* __restrict__ shift,
                               __nv_bfloat16* __restrict__ Ahi,
                               __nv_bfloat16* __restrict__ Alo) {
    int i = blockIdx.x * blockDim.x + threadIdx.x;
    if (i >= Nn * Hh / 4) return;
    int c = (i & (Hh / 4 - 1)) * 4;
    float4 v = ((const float4*)X)[i];
    v.x = fmaxf(fmaf(v.x, scale[c + 0], shift[c + 0]), 0.f);
    v.y = fmaxf(fmaf(v.y, scale[c + 1], shift[c + 1]), 0.f);
    v.z = fmaxf(fmaf(v.z, scale[c + 2], shift[c + 2]), 0.f);
    v.w = fmaxf(fmaf(v.w, scale[c + 3], shift[c + 3]), 0.f);
    float rx, ry, rz, rw;
    uint2 hi, lo;
    hi.x = pack2bf(v.x, v.y, &rx, &ry);
    hi.y = pack2bf(v.z, v.w, &rz, &rw);
    lo.x = pack2bf_only(rx, ry);
    lo.y = pack2bf_only(rz, rw);
    ((uint2*)Ahi)[i] = hi;
    ((uint2*)Alo)[i] = lo;
}

// ---------------- mma.sync bf16x3 GEMM ---------------------------------------
// C[Mr,Nc] fp32 = (Ahi+Alo)[Mr,K] @ (Bhi+Blo)^T  (B stored [Nc,K] row-major)
// CTA tile 128x128, K-tile 64 bf16 (128B rows, SW128 swizzle).
#define SA_HI 0
#define SA_LO 16384
#define SB_HI 32768
#define SB_LO 49152
#define GEMM_SMEM 65536

__global__ __launch_bounds__(256) void mma_gemm_k(
    const __nv_bfloat16* __restrict__ Ahi, const __nv_bfloat16* __restrict__ Alo,
    const __nv_bfloat16* __restrict__ Bhi, const __nv_bfloat16* __restrict__ Blo,
    float* __restrict__ C, int Mr, int K, int Nc) {
    extern __shared__ char smem[];
    const uint32_t sb = smem_u32(smem);
    const int tid = threadIdx.x;
    const int lane = tid & 31, wid = tid >> 5;
    const int wm = (wid >> 2) * 64;  // warp m offset
    const int wn = (wid & 3) * 32;   // warp n offset
    const int m0 = blockIdx.y * 128;
    const int n0 = blockIdx.x * 128;
    const int nkt = K >> 6;

    float acc[4][4][4];
#pragma unroll
    for (int a = 0; a < 4; a++)
#pragma unroll
        for (int b = 0; b < 4; b++)
#pragma unroll
            for (int c = 0; c < 4; c++) acc[a][b][c] = 0.f;

    // global->smem load coords: thread t loads half-row (32 bf16 = 4x16B)
    const int lrow = tid >> 1;
    const int lhalf = tid & 1;
    const bool arow_ok = (m0 + lrow) < Mr;
    const char* pAhi = (const char*)(Ahi + (size_t)(m0 + lrow) * K + lhalf * 32);
    const char* pAlo = (const char*)(Alo + (size_t)(m0 + lrow) * K + lhalf * 32);
    const char* pBhi = (const char*)(Bhi + (size_t)(n0 + lrow) * K + lhalf * 32);
    const char* pBlo = (const char*)(Blo + (size_t)(n0 + lrow) * K + lhalf * 32);

    for (int kt = 0; kt < nkt; kt++) {
        __syncthreads();
        const size_t gk = (size_t)kt * 128;  // 64 bf16 = 128 bytes
#pragma unroll
        for (int j = 0; j < 4; j++) {
            uint32_t so = SW128((uint32_t)(lrow * 128 + lhalf * 64 + j * 16));
            uint4 vh = make_uint4(0, 0, 0, 0), vl = make_uint4(0, 0, 0, 0);
            if (arow_ok) {
                vh = *(const uint4*)(pAhi + gk + j * 16);
                vl = *(const uint4*)(pAlo + gk + j * 16);
            }
            *(uint4*)(smem + SA_HI + so) = vh;
            *(uint4*)(smem + SA_LO + so) = vl;
            *(uint4*)(smem + SB_HI + so) = *(const uint4*)(pBhi + gk + j * 16);
            *(uint4*)(smem + SB_LO + so) = *(const uint4*)(pBlo + gk + j * 16);
        }
        __syncthreads();

#pragma unroll
        for (int ks = 0; ks < 4; ks++) {
            const int k0 = ks * 16;
            const uint32_t ar = wm + (lane & 15);
            const uint32_t ac = k0 + ((lane >> 4) << 3);
            const uint32_t br = wn + (lane & 7) + ((lane >> 4) << 3);
            const uint32_t bc = k0 + (((lane >> 3) & 1) << 3);
            uint32_t bhi[8], blo[8], af[16];
#pragma unroll
            for (int nb = 0; nb < 2; nb++) {
                uint32_t off = SW128((br + nb * 16) * 128 + bc * 2);
                LDSM_X4(bhi[nb * 4 + 0], bhi[nb * 4 + 1], bhi[nb * 4 + 2], bhi[nb * 4 + 3],
                        sb + SB_HI + off);
                LDSM_X4(blo[nb * 4 + 0], blo[nb * 4 + 1], blo[nb * 4 + 2], blo[nb * 4 + 3],
                        sb + SB_LO + off);
            }
#pragma unroll
            for (int mf = 0; mf < 4; mf++) {
                uint32_t off = SW128((ar + mf * 16) * 128 + ac * 2);
                LDSM_X4(af[mf * 4 + 0], af[mf * 4 + 1], af[mf * 4 + 2], af[mf * 4 + 3],
                        sb + SA_HI + off);
            }
#pragma unroll
            for (int mf = 0; mf < 4; mf++)
#pragma unroll
                for (int nf = 0; nf < 4; nf++) {
                    int bi = (nf >> 1) * 4 + (nf & 1) * 2;
                    MMA16816(acc[mf][nf], af[mf * 4], af[mf * 4 + 1], af[mf * 4 + 2],
                             af[mf * 4 + 3], bhi[bi], bhi[bi + 1]);
                    MMA16816(acc[mf][nf], af[mf * 4], af[mf * 4 + 1], af[mf * 4 + 2],
                             af[mf * 4 + 3], blo[bi], blo[bi + 1]);
                }
#pragma unroll
            for (int mf = 0; mf < 4; mf++) {
                uint32_t off = SW128((ar + mf * 16) * 128 + ac * 2);
                LDSM_X4(af[mf * 4 + 0], af[mf * 4 + 1], af[mf * 4 + 2], af[mf * 4 + 3],
                        sb + SA_LO + off);
            }
#pragma unroll
            for (int mf = 0; mf < 4; mf++)
#pragma unroll
                for (int nf = 0; nf < 4; nf++) {
                    int bi = (nf >> 1) * 4 + (nf & 1) * 2;
                    MMA16816(acc[mf][nf], af[mf * 4], af[mf * 4 + 1], af[mf * 4 + 2],
                             af[mf * 4 + 3], bhi[bi], bhi[bi + 1]);
                }
        }
    }

    // epilogue: acc -> C
#pragma unroll
    for (int mf = 0; mf < 4; mf++) {
        int r = m0 + wm + mf * 16 + (lane >> 2);
#pragma unroll
        for (int nf = 0; nf < 4; nf++) {
            int col = n0 + wn + nf * 8 + (lane & 3) * 2;
            if (r < Mr)
                *(float2*)&C[(size_t)r * Nc + col] = make_float2(acc[mf][nf][0], acc[mf][nf][1]);
            if (r + 8 < Mr)
                *(float2*)&C[(size_t)(r + 8) * Nc + col] = make_float2(acc[mf][nf][2], acc[mf][nf][3]);
        }
    }
}

// ---------------- BN stats / apply ------------------------------------------
__global__ void colstats_k(const float* __restrict__ X, int C, float* __restrict__ sums) {
    int col = blockIdx.x * 32 + threadIdx.x;
    float s = 0.f, s2 = 0.f;
    for (int r = blockIdx.y * 8 + threadIdx.y; r < Nn; r += gridDim.y * 8) {
        float v = X[(size_t)r * C + col];
        s += v;
        s2 += v * v;
    }
    __shared__ float sh[2][8][32];
    sh[0][threadIdx.y][threadIdx.x] = s;
    sh[1][threadIdx.y][threadIdx.x] = s2;
    __syncthreads();
    if (threadIdx.y == 0) {
#pragma unroll
        for (int k = 1; k < 8; k++) {
            s += sh[0][k][threadIdx.x];
            s2 += sh[1][k][threadIdx.x];
        }
        atomicAdd(&sums[col], s);
        atomicAdd(&sums[C + col], s2);
    }
}

__global__ void bn_finalize_k(const float* __restrict__ sums,
                              const float* __restrict__ g,
                              const float* __restrict__ be,
                              float* __restrict__ scale, float* __restrict__ shift, int C) {
    int c = blockIdx.x * blockDim.x + threadIdx.x;
    if (c >= C) return;
    float mean = sums[c] * (1.f / Nn);
    float var = sums[C + c] * (1.f / Nn) - mean * mean;
    float sc = g[c] * rsqrtf(var + 1e-5f);
    scale[c] = sc;
    shift[c] = be[c] - mean * sc;
}

__global__ void bn_apply_k(const float* __restrict__ X,
                           const float* __restrict__ scale,
                           const float* __restrict__ shift,
                           float* __restrict__ Y, int do_relu) {
    int i = blockIdx.x * blockDim.x + threadIdx.x;
    if (i >= Nn * Ee / 4) return;
    int c = (i & 63) * 4;
    float4 v = ((const float4*)X)[i];
    v.x = fmaf(v.x, scale[c + 0], shift[c + 0]);
    v.y = fmaf(v.y, scale[c + 1], shift[c + 1]);
    v.z = fmaf(v.z, scale[c + 2], shift[c + 2]);
    v.w = fmaf(v.w, scale[c + 3], shift[c + 3]);
    if (do_relu) {
        v.x = fmaxf(v.x, 0.f); v.y = fmaxf(v.y, 0.f);
        v.z = fmaxf(v.z, 0.f); v.w = fmaxf(v.w, 0.f);
    }
    ((float4*)Y)[i] = v;
}

// ---------------- host orchestration ----------------------------------------
struct Scratch {
    float *h, *agg, *t1, *hB;
    float *sumsH, *sumsE, *scaleH, *shiftH, *scaleE, *shiftE, *mask;
    __nv_bfloat16 *A1hi, *A1lo, *A2hi, *A2lo;
    __nv_bfloat16 *W1Thi, *W1Tlo, *W2Thi, *W2Tlo;
};

static void run_conv(const Scratch& S, int conv,
                     const int* src, const int* dst, int M,
                     const int* attr, const float* bemb,
                     const float* eps,
                     const float* g1, const float* be1,
                     const float* bn_g, const float* bn_b,
                     const float* mask, int relu_out) {
    prep_zero_k<<<(Nn * Ee / 4 + 255) / 256, 256>>>();

    int warps_blocks = (M * 32 + 255) / 256;
    if (attr)
        scatter_bond_k<<<warps_blocks, 256>>>(S.h, src, dst, attr, bemb, S.agg, M);
    else
        scatter_plain_k<<<warps_blocks, 256>>>(S.h, src, dst, S.agg, M);

    combine_split_k<<<(Nn * Ee / 4 + 255) / 256, 256>>>(S.h, S.agg, mask, eps, S.A1hi, S.A1lo);

    dim3 g1d(Hh / 128, (Nn + 127) / 128);
    mma_gemm_k<<<g1d, 256, GEMM_SMEM>>>(S.A1hi, S.A1lo,
                                        S.W1Thi + (size_t)conv * Hh * Ee,
                                        S.W1Tlo + (size_t)conv * Hh * Ee,
                                        S.t1, Nn, Ee, Hh);

    colstats_k<<<dim3(Hh / 32, 40), dim3(32, 8)>>>(S.t1, Hh, S.sumsH);
    bn_finalize_k<<<(Hh + 255) / 256, 256>>>(S.sumsH, g1, be1, S.scaleH, S.shiftH, Hh);
    bnrelu_split_k<<<(Nn * Hh / 4 + 255) / 256, 256>>>(S.t1, S.scaleH, S.shiftH, S.A2hi, S.A2lo);

    dim3 g2d(Ee / 128, (Nn + 127) / 128);
    mma_gemm_k<<<g2d, 256, GEMM_SMEM>>>(S.A2hi, S.A2lo,
                                        S.W2Thi + (size_t)conv * Ee * Hh,
                                        S.W2Tlo + (size_t)conv * Ee * Hh,
                                        S.hB, Nn, Hh, Ee);

    colstats_k<<<dim3(Ee / 32, 40), dim3(32, 8)>>>(S.hB, Ee, S.sumsE);
    bn_finalize_k<<<(Ee + 255) / 256, 256>>>(S.sumsE, bn_g, bn_b, S.scaleE, S.shiftE, Ee);
    bn_apply_k<<<(Nn * Ee / 4 + 255) / 256, 256>>>(S.hB, S.scaleE, S.shiftE, S.h, relu_out);
}

extern "C" void kernel_launch(void* const* d_in, const int* in_sizes, int n_in,
                              void* d_out, int out_size) {
    const int* x       = (const int*)d_in[0];
    const int* ei      = (const int*)d_in[1];
    const int* ea      = (const int*)d_in[2];
    const int* xei     = (const int*)d_in[3];
    const void* mask_raw = d_in[4];
    const float* atom_emb = (const float*)d_in[5];
    const float* bond_emb = (const float*)d_in[6];
    const float* eps_m = (const float*)d_in[7];
    const float* W1_m  = (const float*)d_in[8];
    // d_in[9] = b1_m (unused: cancelled by BN)
    const float* g1_m  = (const float*)d_in[10];
    const float* be1_m = (const float*)d_in[11];
    const float* W2_m  = (const float*)d_in[12];
    // d_in[13] = b2_m (unused: cancelled by BN)
    const float* bn_g_m = (const float*)d_in[14];
    const float* bn_b_m = (const float*)d_in[15];
    const float* eps_e = (const float*)d_in[16];
    const float* W1_e  = (const float*)d_in[17];
    const float* g1_e  = (const float*)d_in[18];
    const float* be1_e = (const float*)d_in[19];
    const float* W2_e  = (const float*)d_in[20];
    const float* bn_g_e = (const float*)d_in[21];
    const float* bn_b_e = (const float*)d_in[22];

    const int M  = in_sizes[1] / 2;
    const int MX = in_sizes[3] / 2;

    cudaFuncSetAttribute(mma_gemm_k, cudaFuncAttributeMaxDynamicSharedMemorySize, GEMM_SMEM);

    Scratch S;
    cudaGetSymbolAddress((void**)&S.h, g_h);
    cudaGetSymbolAddress((void**)&S.agg, g_agg);
    cudaGetSymbolAddress((void**)&S.t1, g_t1);
    cudaGetSymbolAddress((void**)&S.hB, g_hB);
    cudaGetSymbolAddress((void**)&S.sumsH, g_sumsH);
    cudaGetSymbolAddress((void**)&S.sumsE, g_sumsE);
    cudaGetSymbolAddress((void**)&S.scaleH, g_scaleH);
    cudaGetSymbolAddress((void**)&S.shiftH, g_shiftH);
    cudaGetSymbolAddress((void**)&S.scaleE, g_scaleE);
    cudaGetSymbolAddress((void**)&S.shiftE, g_shiftE);
    cudaGetSymbolAddress((void**)&S.mask, g_mask);
    cudaGetSymbolAddress((void**)&S.A1hi, g_A1hi);
    cudaGetSymbolAddress((void**)&S.A1lo, g_A1lo);
    cudaGetSymbolAddress((void**)&S.A2hi, g_A2hi);
    cudaGetSymbolAddress((void**)&S.A2lo, g_A2lo);
    cudaGetSymbolAddress((void**)&S.W1Thi, g_W1Thi);
    cudaGetSymbolAddress((void**)&S.W1Tlo, g_W1Tlo);
    cudaGetSymbolAddress((void**)&S.W2Thi, g_W2Thi);
    cudaGetSymbolAddress((void**)&S.W2Tlo, g_W2Tlo);

    const int* src  = ei;
    const int* dstp = ei + M;
    const int* esrc = xei;
    const int* edst = xei + MX;

    // --- pre-transpose + split all weights (conv order: 3l, 3l+1, 3l+2) ----
    for (int l = 0; l < Ll; l++) {
        const float* w1s[3] = { W1_m + (size_t)l * Ee * Hh,
                                W1_e + (size_t)(l * 2 + 0) * Ee * Hh,
                                W1_e + (size_t)(l * 2 + 1) * Ee * Hh };
        const float* w2s[3] = { W2_m + (size_t)l * Hh * Ee,
                                W2_e + (size_t)(l * 2 + 0) * Hh * Ee,
                                W2_e + (size_t)(l * 2 + 1) * Hh * Ee };
        for (int j = 0; j < 3; j++) {
            int c = l * 3 + j;
            wsplit_k<<<dim3(Ee / 32, Hh / 32), dim3(32, 8)>>>(
                w1s[j], S.W1Thi + (size_t)c * Hh * Ee, S.W1Tlo + (size_t)c * Hh * Ee, Ee, Hh);
            wsplit_k<<<dim3(Hh / 32, Ee / 32), dim3(32, 8)>>>(
                w2s[j], S.W2Thi + (size_t)c * Ee * Hh, S.W2Tlo + (size_t)c * Ee * Hh, Hh, Ee);
        }
    }

    detect_mask_k<<<1, 256>>>(mask_raw);
    convert_mask_k<<<(Nn + 255) / 256, 256>>>(mask_raw);

    atom_encode_k<<<Nn, 64>>>(x, atom_emb, S.h);

    for (int l = 0; l < Ll; l++) {
        run_conv(S, l * 3 + 0, src, dstp, M, ea, bond_emb,
                 eps_m + l,
                 g1_m + (size_t)l * Hh, be1_m + (size_t)l * Hh,
                 bn_g_m + (size_t)l * Ee, bn_b_m + (size_t)l * Ee,
                 nullptr, 1);

        int s0 = l * 2, s1 = l * 2 + 1;
        run_conv(S, l * 3 + 1, esrc, edst, MX, nullptr, nullptr,
                 eps_e + s0,
                 g1_e + (size_t)s0 * Hh, be1_e + (size_t)s0 * Hh,
                 bn_g_e + (size_t)s0 * Ee, bn_b_e + (size_t)s0 * Ee,
                 S.mask, 1);

        run_conv(S, l * 3 + 2, edst, esrc, MX, nullptr, nullptr,
                 eps_e + s1,
                 g1_e + (size_t)s1 * Hh, be1_e + (size_t)s1 * Hh,
                 bn_g_e + (size_t)s1 * Ee, bn_b_e + (size_t)s1 * Ee,
                 S.mask, (l < Ll - 1) ? 1 : 0);
    }

    cudaMemcpyAsync(d_out, S.h, (size_t)Nn * Ee * sizeof(float),
                    cudaMemcpyDeviceToDevice, 0);
}

// round 5
// speedup vs baseline: 1.9326x; 1.1338x over previous
#include <cuda_runtime.h>
#include <cuda_fp16.h>
#include <cstddef>
#include <cstdint>

#define Nn 20000
#define Ee 256
#define Hh 512
#define Ll 5
#define NCONV 15

// ---------------- scratch (device globals; no allocations allowed) ----------
__device__ float g_h[Nn * Ee];
__device__ float g_agg[Nn * Ee];
__device__ float g_t1[Nn * Hh];
__device__ float g_hB[Nn * Ee];
__device__ float g_sumsH[2 * Hh];
__device__ float g_sumsE[2 * Ee];
__device__ float g_scaleH[Hh];
__device__ float g_shiftH[Hh];
__device__ float g_scaleE[Ee];
__device__ float g_shiftE[Ee];
__device__ float g_mask[Nn];
__device__ int   g_mask_dtype;

// fp16 split operands
__device__ __half g_A1hi[Nn * Ee];
__device__ __half g_A1lo[Nn * Ee];
__device__ __half g_A2hi[Nn * Hh];
__device__ __half g_A2lo[Nn * Hh];
// pre-transposed weights: W1T[c]: [Hh rows, Ee cols]; W2T[c]: [Ee rows, Hh cols]
__device__ __half g_W1Thi[NCONV * Hh * Ee];
__device__ __half g_W1Tlo[NCONV * Hh * Ee];
__device__ __half g_W2Thi[NCONV * Ee * Hh];
__device__ __half g_W2Tlo[NCONV * Ee * Hh];

// ---------------- helpers ----------------------------------------------------
__device__ __forceinline__ uint32_t smem_u32(const void* p) {
    uint32_t a;
    asm("{ .reg .u64 t; cvta.to.shared.u64 t, %1; cvt.u32.u64 %0, t; }" : "=r"(a) : "l"(p));
    return a;
}
#define SW128(off) ((off) ^ (((off) >> 3) & 0x70))

#define LDSM_X4(r0, r1, r2, r3, addr) \
    asm volatile("ldmatrix.sync.aligned.m8n8.x4.shared.b16 {%0,%1,%2,%3}, [%4];" \
                 : "=r"(r0), "=r"(r1), "=r"(r2), "=r"(r3) : "r"(addr))

#define MMA16816(d, a0, a1, a2, a3, b0, b1) \
    asm volatile("mma.sync.aligned.m16n8k16.row.col.f32.f16.f16.f32 " \
                 "{%0,%1,%2,%3}, {%4,%5,%6,%7}, {%8,%9}, {%0,%1,%2,%3};" \
                 : "+f"((d)[0]), "+f"((d)[1]), "+f"((d)[2]), "+f"((d)[3]) \
                 : "r"(a0), "r"(a1), "r"(a2), "r"(a3), "r"(b0), "r"(b1))

#define CP_ASYNC16(dst, src, sz) \
    asm volatile("cp.async.cg.shared.global [%0], [%1], 16, %2;" \
                 :: "r"(dst), "l"(src), "r"(sz))
#define CP_COMMIT() asm volatile("cp.async.commit_group;" ::: "memory")
#define CP_WAIT0() asm volatile("cp.async.wait_group 0;" ::: "memory")
#define CP_WAIT1() asm volatile("cp.async.wait_group 1;" ::: "memory")

// ---------------- mask dtype handling ---------------------------------------
__global__ void detect_mask_k(const void* mask) {
    __shared__ int not_i32, not_f32;
    if (threadIdx.x == 0) { not_i32 = 0; not_f32 = 0; }
    __syncthreads();
    const unsigned* w = (const unsigned*)mask;
    int bad_i = 0, bad_f = 0;
    for (int i = threadIdx.x; i < Nn / 4; i += blockDim.x) {
        unsigned v = w[i];
        if (v > 1u) bad_i = 1;
        if (v != 0u && v != 0x3F800000u) bad_f = 1;
    }
    if (bad_i) atomicOr(&not_i32, 1);
    if (bad_f) atomicOr(&not_f32, 1);
    __syncthreads();
    if (threadIdx.x == 0) {
        if (!not_i32) g_mask_dtype = 0;
        else if (!not_f32) g_mask_dtype = 1;
        else g_mask_dtype = 2;
    }
}
__global__ void convert_mask_k(const void* mask) {
    int n = blockIdx.x * blockDim.x + threadIdx.x;
    if (n >= Nn) return;
    int dt = g_mask_dtype;
    float m;
    if (dt == 0)      m = (((const int*)mask)[n] != 0) ? 1.f : 0.f;
    else if (dt == 1) m = (((const float*)mask)[n] != 0.f) ? 1.f : 0.f;
    else              m = (((const unsigned char*)mask)[n] != 0) ? 1.f : 0.f;
    g_mask[n] = m;
}

// ---------------- weight transpose + fp16 split -----------------------------
// W [K,N] fp32 -> WT hi/lo [N,K] fp16
__global__ void wsplit_k(const float* __restrict__ W,
                         __half* __restrict__ Thi,
                         __half* __restrict__ Tlo, int K, int N) {
    __shared__ float t[32][33];
    int kb = blockIdx.x * 32, nb = blockIdx.y * 32;
    int tx = threadIdx.x, ty = threadIdx.y;
    for (int i = ty; i < 32; i += 8)
        t[i][tx] = W[(size_t)(kb + i) * N + nb + tx];
    __syncthreads();
    for (int i = ty; i < 32; i += 8) {
        float v = t[tx][i];  // = W[kb+tx][nb+i]
        __half hi = __float2half_rn(v);
        float lo = v - __half2float(hi);
        Thi[(size_t)(nb + i) * K + kb + tx] = hi;
        Tlo[(size_t)(nb + i) * K + kb + tx] = __float2half_rn(lo);
    }
}

// ---------------- misc kernels ----------------------------------------------
__global__ void prep_zero_k() {
    int i = blockIdx.x * blockDim.x + threadIdx.x;
    if (i < Nn * Ee / 4) ((float4*)g_agg)[i] = make_float4(0.f, 0.f, 0.f, 0.f);
    if (i < 2 * Hh) g_sumsH[i] = 0.f;
    if (i < 2 * Ee) g_sumsE[i] = 0.f;
}

__global__ void atom_encode_k(const int* __restrict__ x,
                              const float* __restrict__ emb,
                              float* __restrict__ h) {
    int n = blockIdx.x;
    int t = threadIdx.x;
    float4 acc = make_float4(0.f, 0.f, 0.f, 0.f);
#pragma unroll
    for (int f = 0; f < 9; f++) {
        int idx = __ldg(&x[n * 9 + f]);
        const float4* row = (const float4*)&emb[((size_t)(f * 128 + idx)) * Ee];
        float4 v = row[t];
        acc.x += v.x; acc.y += v.y; acc.z += v.z; acc.w += v.w;
    }
    ((float4*)h)[(size_t)n * (Ee / 4) + t] = acc;
}

__global__ void scatter_bond_k(const float* __restrict__ h,
                               const int* __restrict__ src,
                               const int* __restrict__ dst,
                               const int* __restrict__ attr,
                               const float* __restrict__ bemb,
                               float* __restrict__ agg, int M) {
    int w = (blockIdx.x * blockDim.x + threadIdx.x) >> 5;
    int lane = threadIdx.x & 31;
    if (w >= M) return;
    int s  = __ldg(&src[w]);
    int d  = __ldg(&dst[w]);
    int a0 = __ldg(&attr[w * 3 + 0]);
    int a1 = __ldg(&attr[w * 3 + 1]);
    int a2 = __ldg(&attr[w * 3 + 2]);
    const float* hs = h + (size_t)s * Ee;
    const float* e0 = bemb + (size_t)(0 * 8 + a0) * Ee;
    const float* e1 = bemb + (size_t)(1 * 8 + a1) * Ee;
    const float* e2 = bemb + (size_t)(2 * 8 + a2) * Ee;
    float* ag = agg + (size_t)d * Ee;
#pragma unroll
    for (int j = 0; j < 8; j++) {
        int e = lane + j * 32;
        float v = __ldg(&hs[e]) + __ldg(&e0[e]) + __ldg(&e1[e]) + __ldg(&e2[e]);
        atomicAdd(&ag[e], fmaxf(v, 0.f));
    }
}

__global__ void scatter_plain_k(const float* __restrict__ h,
                                const int* __restrict__ src,
                                const int* __restrict__ dst,
                                float* __restrict__ agg, int M) {
    int w = (blockIdx.x * blockDim.x + threadIdx.x) >> 5;
    int lane = threadIdx.x & 31;
    if (w >= M) return;
    int s = __ldg(&src[w]);
    int d = __ldg(&dst[w]);
    const float* hs = h + (size_t)s * Ee;
    float* ag = agg + (size_t)d * Ee;
#pragma unroll
    for (int j = 0; j < 8; j++) {
        int e = lane + j * 32;
        atomicAdd(&ag[e], fmaxf(__ldg(&hs[e]), 0.f));
    }
}

__device__ __forceinline__ uint32_t pack2h(float a, float b, float* ra, float* rb) {
    __half ha = __float2half_rn(a), hb = __float2half_rn(b);
    *ra = a - __half2float(ha);
    *rb = b - __half2float(hb);
    return (uint32_t)__half_as_ushort(ha) | ((uint32_t)__half_as_ushort(hb) << 16);
}
__device__ __forceinline__ uint32_t pack2h_only(float a, float b) {
    __half ha = __float2half_rn(a), hb = __float2half_rn(b);
    return (uint32_t)__half_as_ushort(ha) | ((uint32_t)__half_as_ushort(hb) << 16);
}

// pre = (1+eps)*(h*mask?) + agg  -> split to fp16 hi/lo (GEMM1 A operand)
__global__ void combine_split_k(const float* __restrict__ h,
                                const float* __restrict__ agg,
                                const float* __restrict__ mask,
                                const float* __restrict__ eps,
                                __half* __restrict__ Ahi,
                                __half* __restrict__ Alo) {
    int i = blockIdx.x * blockDim.x + threadIdx.x;
    if (i >= Nn * Ee / 4) return;
    float e1 = 1.f + __ldg(eps);
    float4 xv = ((const float4*)h)[i];
    if (mask) {
        float m = mask[i >> 6];
        xv.x *= m; xv.y *= m; xv.z *= m; xv.w *= m;
    }
    float4 av = ((const float4*)agg)[i];
    float4 o;
    o.x = fmaf(e1, xv.x, av.x);
    o.y = fmaf(e1, xv.y, av.y);
    o.z = fmaf(e1, xv.z, av.z);
    o.w = fmaf(e1, xv.w, av.w);
    float rx, ry, rz, rw;
    uint2 hi, lo;
    hi.x = pack2h(o.x, o.y, &rx, &ry);
    hi.y = pack2h(o.z, o.w, &rz, &rw);
    lo.x = pack2h_only(rx, ry);
    lo.y = pack2h_only(rz, rw);
    ((uint2*)Ahi)[i] = hi;
    ((uint2*)Alo)[i] = lo;
}

// t1 -> BN(scale,shift) -> relu -> split fp16 hi/lo (GEMM2 A operand)
__global__ void bnrelu_split_k(const float* __restrict__ X,
                               const float* __restrict__ scale,
                               const float* __restrict__ shift,
                               __half* __restrict__ Ahi,
                               __half* __restrict__ Alo) {
    int i = blockIdx.x * blockDim.x + threadIdx.x;
    if (i >= Nn * Hh / 4) return;
    int c = (i & (Hh / 4 - 1)) * 4;
    float4 v = ((const float4*)X)[i];
    v.x = fmaxf(fmaf(v.x, scale[c + 0], shift[c + 0]), 0.f);
    v.y = fmaxf(fmaf(v.y, scale[c + 1], shift[c + 1]), 0.f);
    v.z = fmaxf(fmaf(v.z, scale[c + 2], shift[c + 2]), 0.f);
    v.w = fmaxf(fmaf(v.w, scale[c + 3], shift[c + 3]), 0.f);
    float rx, ry, rz, rw;
    uint2 hi, lo;
    hi.x = pack2h(v.x, v.y, &rx, &ry);
    hi.y = pack2h(v.z, v.w, &rz, &rw);
    lo.x = pack2h_only(rx, ry);
    lo.y = pack2h_only(rz, rw);
    ((uint2*)Ahi)[i] = hi;
    ((uint2*)Alo)[i] = lo;
}

// ---------------- mma.sync fp16x3 GEMM, cp.async 2-stage, fused BN stats -----
// C[Mr,Nc] fp32 = (Ahi+Alo)[Mr,K] @ (Bhi+Blo)^T  (B stored [Nc,K] row-major)
// CTA tile 128x128, K-tile 64 fp16 (128B rows, SW128 swizzle), 2 smem stages.
// Epilogue also accumulates per-column sum/sumsq into sums[2*Nc] via atomics.
#define SA_HI 0
#define SA_LO 16384
#define SB_HI 32768
#define SB_LO 49152
#define STAGE_BYTES 65536
#define GEMM_SMEM 131072

__global__ __launch_bounds__(256) void mma_gemm_k(
    const __half* __restrict__ Ahi, const __half* __restrict__ Alo,
    const __half* __restrict__ Bhi, const __half* __restrict__ Blo,
    float* __restrict__ C, float* __restrict__ sums, int Mr, int K, int Nc) {
    extern __shared__ char smem[];
    const uint32_t sb = smem_u32(smem);
    const int tid = threadIdx.x;
    const int lane = tid & 31, wid = tid >> 5;
    const int wm = (wid >> 2) * 64;  // warp m offset
    const int wn = (wid & 3) * 32;   // warp n offset
    const int m0 = blockIdx.y * 128;
    const int n0 = blockIdx.x * 128;
    const int nkt = K >> 6;

    float acc[4][4][4];
#pragma unroll
    for (int a = 0; a < 4; a++)
#pragma unroll
        for (int b = 0; b < 4; b++)
#pragma unroll
            for (int c = 0; c < 4; c++) acc[a][b][c] = 0.f;

    // global->smem: thread t loads half-row (32 fp16 = 4x16B) per tile
    const int lrow = tid >> 1;
    const int lhalf = tid & 1;
    const bool arow_ok = (m0 + lrow) < Mr;
    const int arow_clamped = arow_ok ? (m0 + lrow) : 0;
    const char* pAhi = (const char*)(Ahi + (size_t)arow_clamped * K + lhalf * 32);
    const char* pAlo = (const char*)(Alo + (size_t)arow_clamped * K + lhalf * 32);
    const char* pBhi = (const char*)(Bhi + (size_t)(n0 + lrow) * K + lhalf * 32);
    const char* pBlo = (const char*)(Blo + (size_t)(n0 + lrow) * K + lhalf * 32);
    const int asz = arow_ok ? 16 : 0;

    auto issue = [&](int stage, int kt) {
        const size_t gk = (size_t)kt * 128;  // 64 fp16 = 128 B
        const uint32_t st = sb + stage * STAGE_BYTES;
#pragma unroll
        for (int j = 0; j < 4; j++) {
            uint32_t so = SW128((uint32_t)(lrow * 128 + lhalf * 64 + j * 16));
            CP_ASYNC16(st + SA_HI + so, pAhi + gk + j * 16, asz);
            CP_ASYNC16(st + SA_LO + so, pAlo + gk + j * 16, asz);
            CP_ASYNC16(st + SB_HI + so, pBhi + gk + j * 16, 16);
            CP_ASYNC16(st + SB_LO + so, pBlo + gk + j * 16, 16);
        }
    };

    issue(0, 0);
    CP_COMMIT();

    for (int kt = 0; kt < nkt; kt++) {
        const int buf = kt & 1;
        if (kt + 1 < nkt) {
            issue(buf ^ 1, kt + 1);
            CP_COMMIT();
            CP_WAIT1();
        } else {
            CP_WAIT0();
        }
        __syncthreads();

        const uint32_t st = sb + buf * STAGE_BYTES;
#pragma unroll
        for (int ks = 0; ks < 4; ks++) {
            const int k0 = ks * 16;
            const uint32_t ar = wm + (lane & 15);
            const uint32_t ac = k0 + ((lane >> 4) << 3);
            const uint32_t br = wn + (lane & 7) + ((lane >> 4) << 3);
            const uint32_t bc = k0 + (((lane >> 3) & 1) << 3);
            uint32_t bhi[8], blo[8], af[16];
#pragma unroll
            for (int nb = 0; nb < 2; nb++) {
                uint32_t off = SW128((br + nb * 16) * 128 + bc * 2);
                LDSM_X4(bhi[nb * 4 + 0], bhi[nb * 4 + 1], bhi[nb * 4 + 2], bhi[nb * 4 + 3],
                        st + SB_HI + off);
                LDSM_X4(blo[nb * 4 + 0], blo[nb * 4 + 1], blo[nb * 4 + 2], blo[nb * 4 + 3],
                        st + SB_LO + off);
            }
#pragma unroll
            for (int mf = 0; mf < 4; mf++) {
                uint32_t off = SW128((ar + mf * 16) * 128 + ac * 2);
                LDSM_X4(af[mf * 4 + 0], af[mf * 4 + 1], af[mf * 4 + 2], af[mf * 4 + 3],
                        st + SA_HI + off);
            }
#pragma unroll
            for (int mf = 0; mf < 4; mf++)
#pragma unroll
                for (int nf = 0; nf < 4; nf++) {
                    int bi = (nf >> 1) * 4 + (nf & 1) * 2;
                    MMA16816(acc[mf][nf], af[mf * 4], af[mf * 4 + 1], af[mf * 4 + 2],
                             af[mf * 4 + 3], bhi[bi], bhi[bi + 1]);
                    MMA16816(acc[mf][nf], af[mf * 4], af[mf * 4 + 1], af[mf * 4 + 2],
                             af[mf * 4 + 3], blo[bi], blo[bi + 1]);
                }
#pragma unroll
            for (int mf = 0; mf < 4; mf++) {
                uint32_t off = SW128((ar + mf * 16) * 128 + ac * 2);
                LDSM_X4(af[mf * 4 + 0], af[mf * 4 + 1], af[mf * 4 + 2], af[mf * 4 + 3],
                        st + SA_LO + off);
            }
#pragma unroll
            for (int mf = 0; mf < 4; mf++)
#pragma unroll
                for (int nf = 0; nf < 4; nf++) {
                    int bi = (nf >> 1) * 4 + (nf & 1) * 2;
                    MMA16816(acc[mf][nf], af[mf * 4], af[mf * 4 + 1], af[mf * 4 + 2],
                             af[mf * 4 + 3], bhi[bi], bhi[bi + 1]);
                }
        }
        __syncthreads();
    }

    // epilogue: acc -> C
#pragma unroll
    for (int mf = 0; mf < 4; mf++) {
        int r = m0 + wm + mf * 16 + (lane >> 2);
#pragma unroll
        for (int nf = 0; nf < 4; nf++) {
            int col = n0 + wn + nf * 8 + (lane & 3) * 2;
            if (r < Mr)
                *(float2*)&C[(size_t)r * Nc + col] = make_float2(acc[mf][nf][0], acc[mf][nf][1]);
            if (r + 8 < Mr)
                *(float2*)&C[(size_t)(r + 8) * Nc + col] = make_float2(acc[mf][nf][2], acc[mf][nf][3]);
        }
    }

    // fused BN column stats (zero-padded rows contribute 0)
#pragma unroll
    for (int nf = 0; nf < 4; nf++) {
        float s0 = 0.f, s1 = 0.f, q0 = 0.f, q1 = 0.f;
#pragma unroll
        for (int mf = 0; mf < 4; mf++) {
            float a0 = acc[mf][nf][0], a1 = acc[mf][nf][1];
            float a2 = acc[mf][nf][2], a3 = acc[mf][nf][3];
            s0 += a0 + a2; s1 += a1 + a3;
            q0 += a0 * a0 + a2 * a2; q1 += a1 * a1 + a3 * a3;
        }
#pragma unroll
        for (int off = 4; off < 32; off <<= 1) {
            s0 += __shfl_xor_sync(0xffffffff, s0, off);
            s1 += __shfl_xor_sync(0xffffffff, s1, off);
            q0 += __shfl_xor_sync(0xffffffff, q0, off);
            q1 += __shfl_xor_sync(0xffffffff, q1, off);
        }
        if (lane < 4) {
            int c = n0 + wn + nf * 8 + lane * 2;
            atomicAdd(&sums[c], s0);
            atomicAdd(&sums[c + 1], s1);
            atomicAdd(&sums[Nc + c], q0);
            atomicAdd(&sums[Nc + c + 1], q1);
        }
    }
}

// ---------------- BN finalize / apply ----------------------------------------
__global__ void bn_finalize_k(const float* __restrict__ sums,
                              const float* __restrict__ g,
                              const float* __restrict__ be,
                              float* __restrict__ scale, float* __restrict__ shift, int C) {
    int c = blockIdx.x * blockDim.x + threadIdx.x;
    if (c >= C) return;
    float mean = sums[c] * (1.f / Nn);
    float var = sums[C + c] * (1.f / Nn) - mean * mean;
    float sc = g[c] * rsqrtf(var + 1e-5f);
    scale[c] = sc;
    shift[c] = be[c] - mean * sc;
}

__global__ void bn_apply_k(const float* __restrict__ X,
                           const float* __restrict__ scale,
                           const float* __restrict__ shift,
                           float* __restrict__ Y, int do_relu) {
    int i = blockIdx.x * blockDim.x + threadIdx.x;
    if (i >= Nn * Ee / 4) return;
    int c = (i & 63) * 4;
    float4 v = ((const float4*)X)[i];
    v.x = fmaf(v.x, scale[c + 0], shift[c + 0]);
    v.y = fmaf(v.y, scale[c + 1], shift[c + 1]);
    v.z = fmaf(v.z, scale[c + 2], shift[c + 2]);
    v.w = fmaf(v.w, scale[c + 3], shift[c + 3]);
    if (do_relu) {
        v.x = fmaxf(v.x, 0.f); v.y = fmaxf(v.y, 0.f);
        v.z = fmaxf(v.z, 0.f); v.w = fmaxf(v.w, 0.f);
    }
    ((float4*)Y)[i] = v;
}

// ---------------- host orchestration ----------------------------------------
struct Scratch {
    float *h, *agg, *t1, *hB;
    float *sumsH, *sumsE, *scaleH, *shiftH, *scaleE, *shiftE, *mask;
    __half *A1hi, *A1lo, *A2hi, *A2lo;
    __half *W1Thi, *W1Tlo, *W2Thi, *W2Tlo;
};

static void run_conv(const Scratch& S, int conv,
                     const int* src, const int* dst, int M,
                     const int* attr, const float* bemb,
                     const float* eps,
                     const float* g1, const float* be1,
                     const float* bn_g, const float* bn_b,
                     const float* mask, int relu_out) {
    prep_zero_k<<<(Nn * Ee / 4 + 255) / 256, 256>>>();

    int warps_blocks = (M * 32 + 255) / 256;
    if (attr)
        scatter_bond_k<<<warps_blocks, 256>>>(S.h, src, dst, attr, bemb, S.agg, M);
    else
        scatter_plain_k<<<warps_blocks, 256>>>(S.h, src, dst, S.agg, M);

    combine_split_k<<<(Nn * Ee / 4 + 255) / 256, 256>>>(S.h, S.agg, mask, eps, S.A1hi, S.A1lo);

    dim3 g1d(Hh / 128, (Nn + 127) / 128);
    mma_gemm_k<<<g1d, 256, GEMM_SMEM>>>(S.A1hi, S.A1lo,
                                        S.W1Thi + (size_t)conv * Hh * Ee,
                                        S.W1Tlo + (size_t)conv * Hh * Ee,
                                        S.t1, S.sumsH, Nn, Ee, Hh);

    bn_finalize_k<<<(Hh + 255) / 256, 256>>>(S.sumsH, g1, be1, S.scaleH, S.shiftH, Hh);
    bnrelu_split_k<<<(Nn * Hh / 4 + 255) / 256, 256>>>(S.t1, S.scaleH, S.shiftH, S.A2hi, S.A2lo);

    dim3 g2d(Ee / 128, (Nn + 127) / 128);
    mma_gemm_k<<<g2d, 256, GEMM_SMEM>>>(S.A2hi, S.A2lo,
                                        S.W2Thi + (size_t)conv * Ee * Hh,
                                        S.W2Tlo + (size_t)conv * Ee * Hh,
                                        S.hB, S.sumsE, Nn, Hh, Ee);

    bn_finalize_k<<<(Ee + 255) / 256, 256>>>(S.sumsE, bn_g, bn_b, S.scaleE, S.shiftE, Ee);
    bn_apply_k<<<(Nn * Ee / 4 + 255) / 256, 256>>>(S.hB, S.scaleE, S.shiftE, S.h, relu_out);
}

extern "C" void kernel_launch(void* const* d_in, const int* in_sizes, int n_in,
                              void* d_out, int out_size) {
    const int* x       = (const int*)d_in[0];
    const int* ei      = (const int*)d_in[1];
    const int* ea      = (const int*)d_in[2];
    const int* xei     = (const int*)d_in[3];
    const void* mask_raw = d_in[4];
    const float* atom_emb = (const float*)d_in[5];
    const float* bond_emb = (const float*)d_in[6];
    const float* eps_m = (const float*)d_in[7];
    const float* W1_m  = (const float*)d_in[8];
    // d_in[9] = b1_m (unused: cancelled by BN)
    const float* g1_m  = (const float*)d_in[10];
    const float* be1_m = (const float*)d_in[11];
    const float* W2_m  = (const float*)d_in[12];
    // d_in[13] = b2_m (unused: cancelled by BN)
    const float* bn_g_m = (const float*)d_in[14];
    const float* bn_b_m = (const float*)d_in[15];
    const float* eps_e = (const float*)d_in[16];
    const float* W1_e  = (const float*)d_in[17];
    const float* g1_e  = (const float*)d_in[18];
    const float* be1_e = (const float*)d_in[19];
    const float* W2_e  = (const float*)d_in[20];
    const float* bn_g_e = (const float*)d_in[21];
    const float* bn_b_e = (const float*)d_in[22];

    const int M  = in_sizes[1] / 2;
    const int MX = in_sizes[3] / 2;

    cudaFuncSetAttribute(mma_gemm_k, cudaFuncAttributeMaxDynamicSharedMemorySize, GEMM_SMEM);

    Scratch S;
    cudaGetSymbolAddress((void**)&S.h, g_h);
    cudaGetSymbolAddress((void**)&S.agg, g_agg);
    cudaGetSymbolAddress((void**)&S.t1, g_t1);
    cudaGetSymbolAddress((void**)&S.hB, g_hB);
    cudaGetSymbolAddress((void**)&S.sumsH, g_sumsH);
    cudaGetSymbolAddress((void**)&S.sumsE, g_sumsE);
    cudaGetSymbolAddress((void**)&S.scaleH, g_scaleH);
    cudaGetSymbolAddress((void**)&S.shiftH, g_shiftH);
    cudaGetSymbolAddress((void**)&S.scaleE, g_scaleE);
    cudaGetSymbolAddress((void**)&S.shiftE, g_shiftE);
    cudaGetSymbolAddress((void**)&S.mask, g_mask);
    cudaGetSymbolAddress((void**)&S.A1hi, g_A1hi);
    cudaGetSymbolAddress((void**)&S.A1lo, g_A1lo);
    cudaGetSymbolAddress((void**)&S.A2hi, g_A2hi);
    cudaGetSymbolAddress((void**)&S.A2lo, g_A2lo);
    cudaGetSymbolAddress((void**)&S.W1Thi, g_W1Thi);
    cudaGetSymbolAddress((void**)&S.W1Tlo, g_W1Tlo);
    cudaGetSymbolAddress((void**)&S.W2Thi, g_W2Thi);
    cudaGetSymbolAddress((void**)&S.W2Tlo, g_W2Tlo);

    const int* src  = ei;
    const int* dstp = ei + M;
    const int* esrc = xei;
    const int* edst = xei + MX;

    // --- pre-transpose + split all weights (conv order: 3l, 3l+1, 3l+2) ----
    for (int l = 0; l < Ll; l++) {
        const float* w1s[3] = { W1_m + (size_t)l * Ee * Hh,
                                W1_e + (size_t)(l * 2 + 0) * Ee * Hh,
                                W1_e + (size_t)(l * 2 + 1) * Ee * Hh };
        const float* w2s[3] = { W2_m + (size_t)l * Hh * Ee,
                                W2_e + (size_t)(l * 2 + 0) * Hh * Ee,
                                W2_e + (size_t)(l * 2 + 1) * Hh * Ee };
        for (int j = 0; j < 3; j++) {
            int c = l * 3 + j;
            wsplit_k<<<dim3(Ee / 32, Hh / 32), dim3(32, 8)>>>(
                w1s[j], S.W1Thi + (size_t)c * Hh * Ee, S.W1Tlo + (size_t)c * Hh * Ee, Ee, Hh);
            wsplit_k<<<dim3(Hh / 32, Ee / 32), dim3(32, 8)>>>(
                w2s[j], S.W2Thi + (size_t)c * Ee * Hh, S.W2Tlo + (size_t)c * Ee * Hh, Hh, Ee);
        }
    }

    detect_mask_k<<<1, 256>>>(mask_raw);
    convert_mask_k<<<(Nn + 255) / 256, 256>>>(mask_raw);

    atom_encode_k<<<Nn, 64>>>(x, atom_emb, S.h);

    for (int l = 0; l < Ll; l++) {
        run_conv(S, l * 3 + 0, src, dstp, M, ea, bond_emb,
                 eps_m + l,
                 g1_m + (size_t)l * Hh, be1_m + (size_t)l * Hh,
                 bn_g_m + (size_t)l * Ee, bn_b_m + (size_t)l * Ee,
                 nullptr, 1);

        int s0 = l * 2, s1 = l * 2 + 1;
        run_conv(S, l * 3 + 1, esrc, edst, MX, nullptr, nullptr,
                 eps_e + s0,
                 g1_e + (size_t)s0 * Hh, be1_e + (size_t)s0 * Hh,
                 bn_g_e + (size_t)s0 * Ee, bn_b_e + (size_t)s0 * Ee,
                 S.mask, 1);

        run_conv(S, l * 3 + 2, edst, esrc, MX, nullptr, nullptr,
                 eps_e + s1,
                 g1_e + (size_t)s1 * Hh, be1_e + (size_t)s1 * Hh,
                 bn_g_e + (size_t)s1 * Ee, bn_b_e + (size_t)s1 * Ee,
                 S.mask, (l < Ll - 1) ? 1 : 0);
    }

    cudaMemcpyAsync(d_out, S.h, (size_t)Nn * Ee * sizeof(float),
                    cudaMemcpyDeviceToDevice, 0);
}

// round 6
// speedup vs baseline: 2.0600x; 1.0659x over previous
#include <cuda_runtime.h>
#include <cuda_fp16.h>
#include <cstddef>
#include <cstdint>

#define Nn 20000
#define Ee 256
#define Hh 512
#define Ll 5
#define NCONV 15
#define MB_CAP 320000
#define MX_CAP 160000

// ---------------- scratch (device globals; no allocations allowed) ----------
__device__ float g_h[Nn * Ee];      // atom-encoder output (conv0 input)
__device__ float g_hB[Nn * Ee];     // conv output pre-outer-BN
__device__ float g_sumsH[2 * Hh];
__device__ float g_sumsE[2 * Ee];
__device__ float g_scaleH[Hh];
__device__ float g_shiftH[Hh];
__device__ float g_scaleE[Ee];
__device__ float g_shiftE[Ee];
__device__ float g_mask[Nn];
__device__ int   g_mask_dtype;
__device__ float g_idsc[Ee];        // identity BN for conv0 input transform
__device__ float g_idsh[Ee];

// fp16 split operands
__device__ __half g_A1hi[Nn * Ee];
__device__ __half g_A1lo[Nn * Ee];
__device__ __half g_t1hi[Nn * Hh];  // GEMM1 raw output as fp16 pair
__device__ __half g_t1lo[Nn * Hh];
__device__ __half g_A2hi[Nn * Hh];
__device__ __half g_A2lo[Nn * Hh];
// pre-transposed weights
__device__ __half g_W1Thi[NCONV * Hh * Ee];
__device__ __half g_W1Tlo[NCONV * Hh * Ee];
__device__ __half g_W2Thi[NCONV * Ee * Hh];
__device__ __half g_W2Tlo[NCONV * Ee * Hh];

// CSR
__device__ int g_deg[Nn];
__device__ int g_cur[Nn];
__device__ int g_offs_b[Nn + 1], g_offs_l[Nn + 1], g_offs_r[Nn + 1];
__device__ int g_src_b[MB_CAP];
__device__ int g_atr_b[MB_CAP];
__device__ int g_src_l[MX_CAP];
__device__ int g_src_r[MX_CAP];

// ---------------- helpers ----------------------------------------------------
__device__ __forceinline__ uint32_t smem_u32(const void* p) {
    uint32_t a;
    asm("{ .reg .u64 t; cvta.to.shared.u64 t, %1; cvt.u32.u64 %0, t; }" : "=r"(a) : "l"(p));
    return a;
}
#define SW128(off) ((off) ^ (((off) >> 3) & 0x70))

#define LDSM_X4(r0, r1, r2, r3, addr) \
    asm volatile("ldmatrix.sync.aligned.m8n8.x4.shared.b16 {%0,%1,%2,%3}, [%4];" \
                 : "=r"(r0), "=r"(r1), "=r"(r2), "=r"(r3) : "r"(addr))

#define MMA16816(d, a0, a1, a2, a3, b0, b1) \
    asm volatile("mma.sync.aligned.m16n8k16.row.col.f32.f16.f16.f32 " \
                 "{%0,%1,%2,%3}, {%4,%5,%6,%7}, {%8,%9}, {%0,%1,%2,%3};" \
                 : "+f"((d)[0]), "+f"((d)[1]), "+f"((d)[2]), "+f"((d)[3]) \
                 : "r"(a0), "r"(a1), "r"(a2), "r"(a3), "r"(b0), "r"(b1))

#define CP_ASYNC16(dst, src, sz) \
    asm volatile("cp.async.cg.shared.global [%0], [%1], 16, %2;" \
                 :: "r"(dst), "l"(src), "r"(sz))
#define CP_COMMIT() asm volatile("cp.async.commit_group;" ::: "memory")
#define CP_WAIT0() asm volatile("cp.async.wait_group 0;" ::: "memory")
#define CP_WAIT1() asm volatile("cp.async.wait_group 1;" ::: "memory")

__device__ __forceinline__ uint32_t pack2h(float a, float b) {
    __half ha = __float2half_rn(a), hb = __float2half_rn(b);
    return (uint32_t)__half_as_ushort(ha) | ((uint32_t)__half_as_ushort(hb) << 16);
}

// ---------------- mask dtype handling ---------------------------------------
__global__ void detect_mask_k(const void* mask) {
    __shared__ int not_i32, not_f32;
    if (threadIdx.x == 0) { not_i32 = 0; not_f32 = 0; }
    __syncthreads();
    const unsigned* w = (const unsigned*)mask;
    int bad_i = 0, bad_f = 0;
    for (int i = threadIdx.x; i < Nn / 4; i += blockDim.x) {
        unsigned v = w[i];
        if (v > 1u) bad_i = 1;
        if (v != 0u && v != 0x3F800000u) bad_f = 1;
    }
    if (bad_i) atomicOr(&not_i32, 1);
    if (bad_f) atomicOr(&not_f32, 1);
    __syncthreads();
    if (threadIdx.x == 0) {
        if (!not_i32) g_mask_dtype = 0;
        else if (!not_f32) g_mask_dtype = 1;
        else g_mask_dtype = 2;
    }
}
__global__ void convert_mask_k(const void* mask) {
    int n = blockIdx.x * blockDim.x + threadIdx.x;
    if (n >= Nn) return;
    int dt = g_mask_dtype;
    float m;
    if (dt == 0)      m = (((const int*)mask)[n] != 0) ? 1.f : 0.f;
    else if (dt == 1) m = (((const float*)mask)[n] != 0.f) ? 1.f : 0.f;
    else              m = (((const unsigned char*)mask)[n] != 0) ? 1.f : 0.f;
    g_mask[n] = m;
    if (n < Ee) { g_idsc[n] = 1.f; g_idsh[n] = 0.f; }
}

// ---------------- merged weight transpose + fp16 split ------------------------
// z<15: W1 of conv z ([Ee,Hh] -> T [Hh,Ee]); z>=15: W2 of conv z-15 ([Hh,Ee] -> T [Ee,Hh])
__global__ void wsplit_all_k(const float* __restrict__ W1m, const float* __restrict__ W1e,
                             const float* __restrict__ W2m, const float* __restrict__ W2e) {
    int z = blockIdx.z;
    int which = z / NCONV;
    int c = z % NCONV;
    int l = c / 3, j = c % 3;
    const float* W;
    __half *Thi, *Tlo;
    int K, N;
    if (which == 0) {
        K = Ee; N = Hh;
        W = j ? W1e + (size_t)(l * 2 + j - 1) * Ee * Hh : W1m + (size_t)l * Ee * Hh;
        Thi = g_W1Thi + (size_t)c * Hh * Ee;
        Tlo = g_W1Tlo + (size_t)c * Hh * Ee;
    } else {
        K = Hh; N = Ee;
        W = j ? W2e + (size_t)(l * 2 + j - 1) * Hh * Ee : W2m + (size_t)l * Hh * Ee;
        Thi = g_W2Thi + (size_t)c * Ee * Hh;
        Tlo = g_W2Tlo + (size_t)c * Ee * Hh;
    }
    int kb = blockIdx.x * 32, nb = blockIdx.y * 32;
    if (kb >= K || nb >= N) return;
    __shared__ float t[32][33];
    int tx = threadIdx.x, ty = threadIdx.y;
    for (int i = ty; i < 32; i += 8)
        t[i][tx] = W[(size_t)(kb + i) * N + nb + tx];
    __syncthreads();
    for (int i = ty; i < 32; i += 8) {
        float v = t[tx][i];
        __half hi = __float2half_rn(v);
        float lo = v - __half2float(hi);
        Thi[(size_t)(nb + i) * K + kb + tx] = hi;
        Tlo[(size_t)(nb + i) * K + kb + tx] = __float2half_rn(lo);
    }
}

// ---------------- CSR build ---------------------------------------------------
__global__ void zero_deg_k() {
    int i = blockIdx.x * blockDim.x + threadIdx.x;
    if (i < Nn) g_deg[i] = 0;
}
__global__ void hist_k(const int* __restrict__ dst, int M) {
    int e = blockIdx.x * blockDim.x + threadIdx.x;
    if (e < M) atomicAdd(&g_deg[dst[e]], 1);
}
// single-block exclusive scan of g_deg -> offs, also init g_cur
__global__ void scan_k(int* __restrict__ offs) {
    __shared__ int ssum[1024];
    int t = threadIdx.x;
    const int PER = (Nn + 1023) / 1024;  // 20
    int loc[20];
    int s = 0;
#pragma unroll
    for (int i = 0; i < PER; i++) {
        int idx = t * PER + i;
        int v = (idx < Nn) ? g_deg[idx] : 0;
        loc[i] = s;
        s += v;
    }
    ssum[t] = s;
    __syncthreads();
    for (int off = 1; off < 1024; off <<= 1) {
        int v = (t >= off) ? ssum[t - off] : 0;
        __syncthreads();
        ssum[t] += v;
        __syncthreads();
    }
    int pre = (t > 0) ? ssum[t - 1] : 0;
#pragma unroll
    for (int i = 0; i < PER; i++) {
        int idx = t * PER + i;
        if (idx < Nn) {
            offs[idx] = pre + loc[i];
            g_cur[idx] = pre + loc[i];
        }
    }
    if (t == 1023) offs[Nn] = ssum[1023];
}
// fill: materialize src (and packed attr) per CSR slot
__global__ void fill_k(const int* __restrict__ dst, const int* __restrict__ srcv,
                       const int* __restrict__ attr, int M, int cap,
                       int* __restrict__ osrc, int* __restrict__ oatr) {
    int e = blockIdx.x * blockDim.x + threadIdx.x;
    if (e >= M) return;
    int p = atomicAdd(&g_cur[dst[e]], 1);
    if (p >= cap) return;
    osrc[p] = srcv[e];
    if (oatr) oatr[p] = attr[e * 3] | (attr[e * 3 + 1] << 3) | (attr[e * 3 + 2] << 6);
}

// ---------------- atom encoder ------------------------------------------------
__global__ void atom_encode_k(const int* __restrict__ x,
                              const float* __restrict__ emb,
                              float* __restrict__ h) {
    int n = blockIdx.x;
    int t = threadIdx.x;
    float4 acc = make_float4(0.f, 0.f, 0.f, 0.f);
#pragma unroll
    for (int f = 0; f < 9; f++) {
        int idx = __ldg(&x[n * 9 + f]);
        const float4* row = (const float4*)&emb[((size_t)(f * 128 + idx)) * Ee];
        float4 v = row[t];
        acc.x += v.x; acc.y += v.y; acc.z += v.z; acc.w += v.w;
    }
    ((float4*)h)[(size_t)n * (Ee / 4) + t] = acc;
}

// ---------------- fused CSR gather + input-BN + self-term + fp16 split --------
// msg_j = relu( in(Xin[src]) + bond? ), in(x) = max(x*sc+sh, floor)
// pre = (1+eps)*mask*in(Xin[node]) + sum msg  -> split -> A1hi/A1lo
template <bool BOND>
__global__ __launch_bounds__(256) void gather_k(
    const float* __restrict__ Xin,
    const float* __restrict__ insc, const float* __restrict__ insh, int inrelu,
    const int* __restrict__ offs, const int* __restrict__ csrc,
    const int* __restrict__ catr, const float* __restrict__ bemb,
    const float* __restrict__ mask, const float* __restrict__ eps,
    __half* __restrict__ Ahi, __half* __restrict__ Alo) {
    int node = blockIdx.x * 8 + (threadIdx.x >> 5);
    if (node >= Nn) return;
    int lane = threadIdx.x & 31;
    int c0 = lane * 8;
    float flo = inrelu ? 0.f : -3.4e38f;

    float4 sc0 = *(const float4*)&insc[c0], sc1 = *(const float4*)&insc[c0 + 4];
    float4 sh0 = *(const float4*)&insh[c0], sh1 = *(const float4*)&insh[c0 + 4];

    float a0 = 0.f, a1 = 0.f, a2 = 0.f, a3 = 0.f, a4 = 0.f, a5 = 0.f, a6 = 0.f, a7 = 0.f;
    int e0 = __ldg(&offs[node]), e1 = __ldg(&offs[node + 1]);
    for (int e = e0; e < e1; e++) {
        int s = __ldg(&csrc[e]);
        const float4* xr = (const float4*)&Xin[(size_t)s * Ee + c0];
        float4 x0 = __ldg(xr), x1 = __ldg(xr + 1);
        float v0 = fmaxf(fmaf(x0.x, sc0.x, sh0.x), flo);
        float v1 = fmaxf(fmaf(x0.y, sc0.y, sh0.y), flo);
        float v2 = fmaxf(fmaf(x0.z, sc0.z, sh0.z), flo);
        float v3 = fmaxf(fmaf(x0.w, sc0.w, sh0.w), flo);
        float v4 = fmaxf(fmaf(x1.x, sc1.x, sh1.x), flo);
        float v5 = fmaxf(fmaf(x1.y, sc1.y, sh1.y), flo);
        float v6 = fmaxf(fmaf(x1.z, sc1.z, sh1.z), flo);
        float v7 = fmaxf(fmaf(x1.w, sc1.w, sh1.w), flo);
        if (BOND) {
            int mt = __ldg(&catr[e]);
            const float4* b0 = (const float4*)&bemb[(size_t)(mt & 7) * Ee + c0];
            const float4* b1 = (const float4*)&bemb[(size_t)(8 + ((mt >> 3) & 7)) * Ee + c0];
            const float4* b2 = (const float4*)&bemb[(size_t)(16 + ((mt >> 6) & 7)) * Ee + c0];
            float4 p0 = __ldg(b0), p1 = __ldg(b0 + 1);
            float4 q0 = __ldg(b1), q1 = __ldg(b1 + 1);
            float4 r0 = __ldg(b2), r1 = __ldg(b2 + 1);
            v0 += p0.x + q0.x + r0.x; v1 += p0.y + q0.y + r0.y;
            v2 += p0.z + q0.z + r0.z; v3 += p0.w + q0.w + r0.w;
            v4 += p1.x + q1.x + r1.x; v5 += p1.y + q1.y + r1.y;
            v6 += p1.z + q1.z + r1.z; v7 += p1.w + q1.w + r1.w;
        }
        a0 += fmaxf(v0, 0.f); a1 += fmaxf(v1, 0.f);
        a2 += fmaxf(v2, 0.f); a3 += fmaxf(v3, 0.f);
        a4 += fmaxf(v4, 0.f); a5 += fmaxf(v5, 0.f);
        a6 += fmaxf(v6, 0.f); a7 += fmaxf(v7, 0.f);
    }
    // self term
    const float4* xr = (const float4*)&Xin[(size_t)node * Ee + c0];
    float4 x0 = __ldg(xr), x1 = __ldg(xr + 1);
    float s0 = fmaxf(fmaf(x0.x, sc0.x, sh0.x), flo);
    float s1 = fmaxf(fmaf(x0.y, sc0.y, sh0.y), flo);
    float s2 = fmaxf(fmaf(x0.z, sc0.z, sh0.z), flo);
    float s3 = fmaxf(fmaf(x0.w, sc0.w, sh0.w), flo);
    float s4 = fmaxf(fmaf(x1.x, sc1.x, sh1.x), flo);
    float s5 = fmaxf(fmaf(x1.y, sc1.y, sh1.y), flo);
    float s6 = fmaxf(fmaf(x1.z, sc1.z, sh1.z), flo);
    float s7 = fmaxf(fmaf(x1.w, sc1.w, sh1.w), flo);
    float m = mask ? __ldg(&mask[node]) : 1.f;
    float ef = (1.f + __ldg(eps)) * m;
    float p0 = fmaf(ef, s0, a0), p1 = fmaf(ef, s1, a1);
    float p2 = fmaf(ef, s2, a2), p3 = fmaf(ef, s3, a3);
    float p4 = fmaf(ef, s4, a4), p5 = fmaf(ef, s5, a5);
    float p6 = fmaf(ef, s6, a6), p7 = fmaf(ef, s7, a7);
    // split and write 8 halves (16B) per array
    uint4 hi, lo;
    {
        __half h0 = __float2half_rn(p0), h1 = __float2half_rn(p1);
        __half h2 = __float2half_rn(p2), h3 = __float2half_rn(p3);
        __half h4 = __float2half_rn(p4), h5 = __float2half_rn(p5);
        __half h6 = __float2half_rn(p6), h7 = __float2half_rn(p7);
        hi.x = (uint32_t)__half_as_ushort(h0) | ((uint32_t)__half_as_ushort(h1) << 16);
        hi.y = (uint32_t)__half_as_ushort(h2) | ((uint32_t)__half_as_ushort(h3) << 16);
        hi.z = (uint32_t)__half_as_ushort(h4) | ((uint32_t)__half_as_ushort(h5) << 16);
        hi.w = (uint32_t)__half_as_ushort(h6) | ((uint32_t)__half_as_ushort(h7) << 16);
        lo.x = pack2h(p0 - __half2float(h0), p1 - __half2float(h1));
        lo.y = pack2h(p2 - __half2float(h2), p3 - __half2float(h3));
        lo.z = pack2h(p4 - __half2float(h4), p5 - __half2float(h5));
        lo.w = pack2h(p6 - __half2float(h6), p7 - __half2float(h7));
    }
    *(uint4*)&Ahi[(size_t)node * Ee + c0] = hi;
    *(uint4*)&Alo[(size_t)node * Ee + c0] = lo;
}

// ---------------- t1 pair -> BN -> relu -> split (GEMM2 A operand) -----------
__global__ void bnrelu_split_k(const __half* __restrict__ Thi, const __half* __restrict__ Tlo,
                               const float* __restrict__ scale,
                               const float* __restrict__ shift,
                               __half* __restrict__ Ahi, __half* __restrict__ Alo) {
    int i = blockIdx.x * blockDim.x + threadIdx.x;
    if (i >= Nn * Hh / 4) return;
    int c = (i & (Hh / 4 - 1)) * 4;
    uint2 vh = ((const uint2*)Thi)[i];
    uint2 vl = ((const uint2*)Tlo)[i];
    float2 h0 = __half22float2(*(__half2*)&vh.x);
    float2 h1 = __half22float2(*(__half2*)&vh.y);
    float2 l0 = __half22float2(*(__half2*)&vl.x);
    float2 l1 = __half22float2(*(__half2*)&vl.y);
    float x0 = h0.x + l0.x, x1 = h0.y + l0.y, x2 = h1.x + l1.x, x3 = h1.y + l1.y;
    x0 = fmaxf(fmaf(x0, scale[c + 0], shift[c + 0]), 0.f);
    x1 = fmaxf(fmaf(x1, scale[c + 1], shift[c + 1]), 0.f);
    x2 = fmaxf(fmaf(x2, scale[c + 2], shift[c + 2]), 0.f);
    x3 = fmaxf(fmaf(x3, scale[c + 3], shift[c + 3]), 0.f);
    __half q0 = __float2half_rn(x0), q1 = __float2half_rn(x1);
    __half q2 = __float2half_rn(x2), q3 = __float2half_rn(x3);
    uint2 hi, lo;
    hi.x = (uint32_t)__half_as_ushort(q0) | ((uint32_t)__half_as_ushort(q1) << 16);
    hi.y = (uint32_t)__half_as_ushort(q2) | ((uint32_t)__half_as_ushort(q3) << 16);
    lo.x = pack2h(x0 - __half2float(q0), x1 - __half2float(q1));
    lo.y = pack2h(x2 - __half2float(q2), x3 - __half2float(q3));
    ((uint2*)Ahi)[i] = hi;
    ((uint2*)Alo)[i] = lo;
}

// ---------------- mma.sync fp16x3 GEMM, cp.async 2-stage, fused BN stats -----
#define SA_HI 0
#define SA_LO 16384
#define SB_HI 32768
#define SB_LO 49152
#define STAGE_BYTES 65536
#define GEMM_SMEM 131072

template <bool HALF_OUT>
__global__ __launch_bounds__(256) void mma_gemm_k(
    const __half* __restrict__ Ahi, const __half* __restrict__ Alo,
    const __half* __restrict__ Bhi, const __half* __restrict__ Blo,
    float* __restrict__ C, __half* __restrict__ Chi, __half* __restrict__ Clo,
    float* __restrict__ sums, int Mr, int K, int Nc) {
    extern __shared__ char smem[];
    const uint32_t sb = smem_u32(smem);
    const int tid = threadIdx.x;
    const int lane = tid & 31, wid = tid >> 5;
    const int wm = (wid >> 2) * 64;
    const int wn = (wid & 3) * 32;
    const int m0 = blockIdx.y * 128;
    const int n0 = blockIdx.x * 128;
    const int nkt = K >> 6;

    float acc[4][4][4];
#pragma unroll
    for (int a = 0; a < 4; a++)
#pragma unroll
        for (int b = 0; b < 4; b++)
#pragma unroll
            for (int c = 0; c < 4; c++) acc[a][b][c] = 0.f;

    const int lrow = tid >> 1;
    const int lhalf = tid & 1;
    const bool arow_ok = (m0 + lrow) < Mr;
    const int arow_clamped = arow_ok ? (m0 + lrow) : 0;
    const char* pAhi = (const char*)(Ahi + (size_t)arow_clamped * K + lhalf * 32);
    const char* pAlo = (const char*)(Alo + (size_t)arow_clamped * K + lhalf * 32);
    const char* pBhi = (const char*)(Bhi + (size_t)(n0 + lrow) * K + lhalf * 32);
    const char* pBlo = (const char*)(Blo + (size_t)(n0 + lrow) * K + lhalf * 32);
    const int asz = arow_ok ? 16 : 0;

    auto issue = [&](int stage, int kt) {
        const size_t gk = (size_t)kt * 128;
        const uint32_t st = sb + stage * STAGE_BYTES;
#pragma unroll
        for (int j = 0; j < 4; j++) {
            uint32_t so = SW128((uint32_t)(lrow * 128 + lhalf * 64 + j * 16));
            CP_ASYNC16(st + SA_HI + so, pAhi + gk + j * 16, asz);
            CP_ASYNC16(st + SA_LO + so, pAlo + gk + j * 16, asz);
            CP_ASYNC16(st + SB_HI + so, pBhi + gk + j * 16, 16);
            CP_ASYNC16(st + SB_LO + so, pBlo + gk + j * 16, 16);
        }
    };

    issue(0, 0);
    CP_COMMIT();

    for (int kt = 0; kt < nkt; kt++) {
        const int buf = kt & 1;
        if (kt + 1 < nkt) {
            issue(buf ^ 1, kt + 1);
            CP_COMMIT();
            CP_WAIT1();
        } else {
            CP_WAIT0();
        }
        __syncthreads();

        const uint32_t st = sb + buf * STAGE_BYTES;
#pragma unroll
        for (int ks = 0; ks < 4; ks++) {
            const int k0 = ks * 16;
            const uint32_t ar = wm + (lane & 15);
            const uint32_t ac = k0 + ((lane >> 4) << 3);
            const uint32_t br = wn + (lane & 7) + ((lane >> 4) << 3);
            const uint32_t bc = k0 + (((lane >> 3) & 1) << 3);
            uint32_t bhi[8], blo[8], af[16];
#pragma unroll
            for (int nb = 0; nb < 2; nb++) {
                uint32_t off = SW128((br + nb * 16) * 128 + bc * 2);
                LDSM_X4(bhi[nb * 4 + 0], bhi[nb * 4 + 1], bhi[nb * 4 + 2], bhi[nb * 4 + 3],
                        st + SB_HI + off);
                LDSM_X4(blo[nb * 4 + 0], blo[nb * 4 + 1], blo[nb * 4 + 2], blo[nb * 4 + 3],
                        st + SB_LO + off);
            }
#pragma unroll
            for (int mf = 0; mf < 4; mf++) {
                uint32_t off = SW128((ar + mf * 16) * 128 + ac * 2);
                LDSM_X4(af[mf * 4 + 0], af[mf * 4 + 1], af[mf * 4 + 2], af[mf * 4 + 3],
                        st + SA_HI + off);
            }
#pragma unroll
            for (int mf = 0; mf < 4; mf++)
#pragma unroll
                for (int nf = 0; nf < 4; nf++) {
                    int bi = (nf >> 1) * 4 + (nf & 1) * 2;
                    MMA16816(acc[mf][nf], af[mf * 4], af[mf * 4 + 1], af[mf * 4 + 2],
                             af[mf * 4 + 3], bhi[bi], bhi[bi + 1]);
                    MMA16816(acc[mf][nf], af[mf * 4], af[mf * 4 + 1], af[mf * 4 + 2],
                             af[mf * 4 + 3], blo[bi], blo[bi + 1]);
                }
#pragma unroll
            for (int mf = 0; mf < 4; mf++) {
                uint32_t off = SW128((ar + mf * 16) * 128 + ac * 2);
                LDSM_X4(af[mf * 4 + 0], af[mf * 4 + 1], af[mf * 4 + 2], af[mf * 4 + 3],
                        st + SA_LO + off);
            }
#pragma unroll
            for (int mf = 0; mf < 4; mf++)
#pragma unroll
                for (int nf = 0; nf < 4; nf++) {
                    int bi = (nf >> 1) * 4 + (nf & 1) * 2;
                    MMA16816(acc[mf][nf], af[mf * 4], af[mf * 4 + 1], af[mf * 4 + 2],
                             af[mf * 4 + 3], bhi[bi], bhi[bi + 1]);
                }
        }
        __syncthreads();
    }

    // epilogue
#pragma unroll
    for (int mf = 0; mf < 4; mf++) {
        int r = m0 + wm + mf * 16 + (lane >> 2);
#pragma unroll
        for (int nf = 0; nf < 4; nf++) {
            int col = n0 + wn + nf * 8 + (lane & 3) * 2;
            float a0 = acc[mf][nf][0], a1 = acc[mf][nf][1];
            float a2 = acc[mf][nf][2], a3 = acc[mf][nf][3];
            if (HALF_OUT) {
                if (r < Mr) {
                    __half h0 = __float2half_rn(a0), h1 = __float2half_rn(a1);
                    *(uint32_t*)&Chi[(size_t)r * Nc + col] =
                        (uint32_t)__half_as_ushort(h0) | ((uint32_t)__half_as_ushort(h1) << 16);
                    *(uint32_t*)&Clo[(size_t)r * Nc + col] =
                        pack2h(a0 - __half2float(h0), a1 - __half2float(h1));
                }
                if (r + 8 < Mr) {
                    __half h2 = __float2half_rn(a2), h3 = __float2half_rn(a3);
                    *(uint32_t*)&Chi[(size_t)(r + 8) * Nc + col] =
                        (uint32_t)__half_as_ushort(h2) | ((uint32_t)__half_as_ushort(h3) << 16);
                    *(uint32_t*)&Clo[(size_t)(r + 8) * Nc + col] =
                        pack2h(a2 - __half2float(h2), a3 - __half2float(h3));
                }
            } else {
                if (r < Mr)
                    *(float2*)&C[(size_t)r * Nc + col] = make_float2(a0, a1);
                if (r + 8 < Mr)
                    *(float2*)&C[(size_t)(r + 8) * Nc + col] = make_float2(a2, a3);
            }
        }
    }

    // fused BN column stats
#pragma unroll
    for (int nf = 0; nf < 4; nf++) {
        float s0 = 0.f, s1 = 0.f, q0 = 0.f, q1 = 0.f;
#pragma unroll
        for (int mf = 0; mf < 4; mf++) {
            float a0 = acc[mf][nf][0], a1 = acc[mf][nf][1];
            float a2 = acc[mf][nf][2], a3 = acc[mf][nf][3];
            s0 += a0 + a2; s1 += a1 + a3;
            q0 += a0 * a0 + a2 * a2; q1 += a1 * a1 + a3 * a3;
        }
#pragma unroll
        for (int off = 4; off < 32; off <<= 1) {
            s0 += __shfl_xor_sync(0xffffffff, s0, off);
            s1 += __shfl_xor_sync(0xffffffff, s1, off);
            q0 += __shfl_xor_sync(0xffffffff, q0, off);
            q1 += __shfl_xor_sync(0xffffffff, q1, off);
        }
        if (lane < 4) {
            int c = n0 + wn + nf * 8 + lane * 2;
            atomicAdd(&sums[c], s0);
            atomicAdd(&sums[c + 1], s1);
            atomicAdd(&sums[Nc + c], q0);
            atomicAdd(&sums[Nc + c + 1], q1);
        }
    }
}

// ---------------- BN finalize (self-zeroing) / final apply -------------------
__global__ void bn_finalize_k(float* __restrict__ sums,
                              const float* __restrict__ g,
                              const float* __restrict__ be,
                              float* __restrict__ scale, float* __restrict__ shift, int C) {
    int c = blockIdx.x * blockDim.x + threadIdx.x;
    if (c >= C) return;
    float mean = sums[c] * (1.f / Nn);
    float var = sums[C + c] * (1.f / Nn) - mean * mean;
    float sc = g[c] * rsqrtf(var + 1e-5f);
    scale[c] = sc;
    shift[c] = be[c] - mean * sc;
    sums[c] = 0.f;
    sums[C + c] = 0.f;
}

__global__ void bn_apply_k(const float* __restrict__ X,
                           const float* __restrict__ scale,
                           const float* __restrict__ shift,
                           float* __restrict__ Y) {
    int i = blockIdx.x * blockDim.x + threadIdx.x;
    if (i >= Nn * Ee / 4) return;
    int c = (i & 63) * 4;
    float4 v = ((const float4*)X)[i];
    v.x = fmaf(v.x, scale[c + 0], shift[c + 0]);
    v.y = fmaf(v.y, scale[c + 1], shift[c + 1]);
    v.z = fmaf(v.z, scale[c + 2], shift[c + 2]);
    v.w = fmaf(v.w, scale[c + 3], shift[c + 3]);
    ((float4*)Y)[i] = v;
}

// ---------------- host orchestration ----------------------------------------
struct Scratch {
    float *h, *hB;
    float *sumsH, *sumsE, *scaleH, *shiftH, *scaleE, *shiftE, *mask, *idsc, *idsh;
    __half *A1hi, *A1lo, *t1hi, *t1lo, *A2hi, *A2lo;
    __half *W1Thi, *W1Tlo, *W2Thi, *W2Tlo;
    int *offs_b, *offs_l, *offs_r, *src_b, *atr_b, *src_l, *src_r;
};

static void run_conv(const Scratch& S, int conv,
                     const float* Xin, const float* insc, const float* insh, int inrelu,
                     const int* offs, const int* csrc, const int* catr, const float* bemb,
                     const float* eps,
                     const float* g1, const float* be1,
                     const float* bn_g, const float* bn_b,
                     const float* mask) {
    if (catr)
        gather_k<true><<<(Nn + 7) / 8, 256>>>(Xin, insc, insh, inrelu, offs, csrc, catr,
                                              bemb, mask, eps, S.A1hi, S.A1lo);
    else
        gather_k<false><<<(Nn + 7) / 8, 256>>>(Xin, insc, insh, inrelu, offs, csrc, nullptr,
                                               nullptr, mask, eps, S.A1hi, S.A1lo);

    dim3 g1d(Hh / 128, (Nn + 127) / 128);
    mma_gemm_k<true><<<g1d, 256, GEMM_SMEM>>>(S.A1hi, S.A1lo,
                                              S.W1Thi + (size_t)conv * Hh * Ee,
                                              S.W1Tlo + (size_t)conv * Hh * Ee,
                                              nullptr, S.t1hi, S.t1lo, S.sumsH, Nn, Ee, Hh);

    bn_finalize_k<<<(Hh + 255) / 256, 256>>>(S.sumsH, g1, be1, S.scaleH, S.shiftH, Hh);
    bnrelu_split_k<<<(Nn * Hh / 4 + 255) / 256, 256>>>(S.t1hi, S.t1lo, S.scaleH, S.shiftH,
                                                       S.A2hi, S.A2lo);

    dim3 g2d(Ee / 128, (Nn + 127) / 128);
    mma_gemm_k<false><<<g2d, 256, GEMM_SMEM>>>(S.A2hi, S.A2lo,
                                               S.W2Thi + (size_t)conv * Ee * Hh,
                                               S.W2Tlo + (size_t)conv * Ee * Hh,
                                               S.hB, nullptr, nullptr, S.sumsE, Nn, Hh, Ee);

    bn_finalize_k<<<(Ee + 255) / 256, 256>>>(S.sumsE, bn_g, bn_b, S.scaleE, S.shiftE, Ee);
}

extern "C" void kernel_launch(void* const* d_in, const int* in_sizes, int n_in,
                              void* d_out, int out_size) {
    const int* x       = (const int*)d_in[0];
    const int* ei      = (const int*)d_in[1];
    const int* ea      = (const int*)d_in[2];
    const int* xei     = (const int*)d_in[3];
    const void* mask_raw = d_in[4];
    const float* atom_emb = (const float*)d_in[5];
    const float* bond_emb = (const float*)d_in[6];
    const float* eps_m = (const float*)d_in[7];
    const float* W1_m  = (const float*)d_in[8];
    const float* g1_m  = (const float*)d_in[10];
    const float* be1_m = (const float*)d_in[11];
    const float* W2_m  = (const float*)d_in[12];
    const float* bn_g_m = (const float*)d_in[14];
    const float* bn_b_m = (const float*)d_in[15];
    const float* eps_e = (const float*)d_in[16];
    const float* W1_e  = (const float*)d_in[17];
    const float* g1_e  = (const float*)d_in[18];
    const float* be1_e = (const float*)d_in[19];
    const float* W2_e  = (const float*)d_in[20];
    const float* bn_g_e = (const float*)d_in[21];
    const float* bn_b_e = (const float*)d_in[22];

    const int M  = in_sizes[1] / 2;
    const int MX = in_sizes[3] / 2;

    cudaFuncSetAttribute(mma_gemm_k<true>, cudaFuncAttributeMaxDynamicSharedMemorySize, GEMM_SMEM);
    cudaFuncSetAttribute(mma_gemm_k<false>, cudaFuncAttributeMaxDynamicSharedMemorySize, GEMM_SMEM);

    Scratch S;
    cudaGetSymbolAddress((void**)&S.h, g_h);
    cudaGetSymbolAddress((void**)&S.hB, g_hB);
    cudaGetSymbolAddress((void**)&S.sumsH, g_sumsH);
    cudaGetSymbolAddress((void**)&S.sumsE, g_sumsE);
    cudaGetSymbolAddress((void**)&S.scaleH, g_scaleH);
    cudaGetSymbolAddress((void**)&S.shiftH, g_shiftH);
    cudaGetSymbolAddress((void**)&S.scaleE, g_scaleE);
    cudaGetSymbolAddress((void**)&S.shiftE, g_shiftE);
    cudaGetSymbolAddress((void**)&S.mask, g_mask);
    cudaGetSymbolAddress((void**)&S.idsc, g_idsc);
    cudaGetSymbolAddress((void**)&S.idsh, g_idsh);
    cudaGetSymbolAddress((void**)&S.A1hi, g_A1hi);
    cudaGetSymbolAddress((void**)&S.A1lo, g_A1lo);
    cudaGetSymbolAddress((void**)&S.t1hi, g_t1hi);
    cudaGetSymbolAddress((void**)&S.t1lo, g_t1lo);
    cudaGetSymbolAddress((void**)&S.A2hi, g_A2hi);
    cudaGetSymbolAddress((void**)&S.A2lo, g_A2lo);
    cudaGetSymbolAddress((void**)&S.W1Thi, g_W1Thi);
    cudaGetSymbolAddress((void**)&S.W1Tlo, g_W1Tlo);
    cudaGetSymbolAddress((void**)&S.W2Thi, g_W2Thi);
    cudaGetSymbolAddress((void**)&S.W2Tlo, g_W2Tlo);
    cudaGetSymbolAddress((void**)&S.offs_b, g_offs_b);
    cudaGetSymbolAddress((void**)&S.offs_l, g_offs_l);
    cudaGetSymbolAddress((void**)&S.offs_r, g_offs_r);
    cudaGetSymbolAddress((void**)&S.src_b, g_src_b);
    cudaGetSymbolAddress((void**)&S.atr_b, g_atr_b);
    cudaGetSymbolAddress((void**)&S.src_l, g_src_l);
    cudaGetSymbolAddress((void**)&S.src_r, g_src_r);

    const int* src  = ei;
    const int* dstp = ei + M;
    const int* esrc = xei;
    const int* edst = xei + MX;

    // weights: merged transpose + split
    wsplit_all_k<<<dim3(16, 16, 2 * NCONV), dim3(32, 8)>>>(W1_m, W1_e, W2_m, W2_e);

    detect_mask_k<<<1, 256>>>(mask_raw);
    convert_mask_k<<<(Nn + 255) / 256, 256>>>(mask_raw);

    // CSR builds: bond (by dstp), left (by edst), right (by esrc)
    {
        zero_deg_k<<<(Nn + 255) / 256, 256>>>();
        hist_k<<<(M + 255) / 256, 256>>>(dstp, M);
        scan_k<<<1, 1024>>>(S.offs_b);
        fill_k<<<(M + 255) / 256, 256>>>(dstp, src, ea, M, MB_CAP, S.src_b, S.atr_b);

        zero_deg_k<<<(Nn + 255) / 256, 256>>>();
        hist_k<<<(MX + 255) / 256, 256>>>(edst, MX);
        scan_k<<<1, 1024>>>(S.offs_l);
        fill_k<<<(MX + 255) / 256, 256>>>(edst, esrc, nullptr, MX, MX_CAP, S.src_l, nullptr);

        zero_deg_k<<<(Nn + 255) / 256, 256>>>();
        hist_k<<<(MX + 255) / 256, 256>>>(esrc, MX);
        scan_k<<<1, 1024>>>(S.offs_r);
        fill_k<<<(MX + 255) / 256, 256>>>(esrc, edst, nullptr, MX, MX_CAP, S.src_r, nullptr);
    }

    atom_encode_k<<<Nn, 64>>>(x, atom_emb, S.h);

    for (int l = 0; l < Ll; l++) {
        int cc = l * 3;
        // bond conv: input = (l==0 ? atom output w/ identity : hB w/ prev outer BN+relu)
        const float* Xin = (l == 0) ? S.h : S.hB;
        const float* isc = (l == 0) ? S.idsc : S.scaleE;
        const float* ish = (l == 0) ? S.idsh : S.shiftE;
        int irelu = (l == 0) ? 0 : 1;
        run_conv(S, cc, Xin, isc, ish, irelu,
                 S.offs_b, S.src_b, S.atr_b, bond_emb,
                 eps_m + l,
                 g1_m + (size_t)l * Hh, be1_m + (size_t)l * Hh,
                 bn_g_m + (size_t)l * Ee, bn_b_m + (size_t)l * Ee, nullptr);

        int s0 = l * 2, s1 = l * 2 + 1;
        // expander left conv (esrc -> edst): input = hB w/ BN+relu from bond conv
        run_conv(S, cc + 1, S.hB, S.scaleE, S.shiftE, 1,
                 S.offs_l, S.src_l, nullptr, nullptr,
                 eps_e + s0,
                 g1_e + (size_t)s0 * Hh, be1_e + (size_t)s0 * Hh,
                 bn_g_e + (size_t)s0 * Ee, bn_b_e + (size_t)s0 * Ee, S.mask);

        // expander right conv (edst -> esrc)
        run_conv(S, cc + 2, S.hB, S.scaleE, S.shiftE, 1,
                 S.offs_r, S.src_r, nullptr, nullptr,
                 eps_e + s1,
                 g1_e + (size_t)s1 * Hh, be1_e + (size_t)s1 * Hh,
                 bn_g_e + (size_t)s1 * Ee, bn_b_e + (size_t)s1 * Ee, S.mask);
    }

    // final output: BN (no relu) of last conv's hB, straight into d_out
    bn_apply_k<<<(Nn * Ee / 4 + 255) / 256, 256>>>(S.hB, S.scaleE, S.shiftE, (float*)d_out);
}